// round 2
// baseline (speedup 1.0000x reference)
#include <cuda_runtime.h>
#include <cuda_bf16.h>
#include <math.h>

// ---------------------------------------------------------------------------
// Problem constants (fixed by the dataset)
//   B=4, L=1024, d=1024, V=32000, NHEAD=16, hd=64, dff=2048, M = B*L = 4096
// ---------------------------------------------------------------------------
#define MROWS 4096
#define DMODEL 1024
#define VOCAB 32000
#define DFF 2048
#define NH 16
#define HD 64
#define LSEQ 1024

// Scratch in device globals (allocation-free rule)
__device__ float g_P[(long)MROWS * VOCAB];      // 524 MB: vocab probs / attn scores
__device__ float g_A[MROWS * DMODEL];
__device__ float g_tmp[MROWS * DMODEL];
__device__ float g_x1[MROWS * DMODEL];
__device__ float g_x2[MROWS * DMODEL];
__device__ float g_q[MROWS * DMODEL];
__device__ float g_k[MROWS * DMODEL];
__device__ float g_v[MROWS * DMODEL];
__device__ float g_y[MROWS * DMODEL];
__device__ float g_h[MROWS * DFF];

// ---------------------------------------------------------------------------
// General tiled SGEMM: C = epilogue( scale * A@B (+bias) (+addmat) )
//   A is [M,K] row-major. B is [K,N] (bT=0) or [N,K] (bT=1), row-major.
//   Batched via blockIdx.z with split offsets: off = (z/zInner)*sXo + (z%zInner)*sXi
//   Epilogue order: v = acc*scale; v += bias[n]; v += addmat[idx]; act(v);
//                   v = residual[idx] + alpha*v;  write (optionally head-permuted)
//   Requirements used here: M % 128 == 0, K % 16 == 0.  N guarded.
// ---------------------------------------------------------------------------
__global__ void __launch_bounds__(256) gemm_k(
    const float* __restrict__ A, const float* __restrict__ Bm, float* __restrict__ C,
    int M, int N, int K, int bT,
    long sAo, long sAi, long sBo, long sBi, long sCo, long sCi, int zInner, int ldc,
    const float* __restrict__ bias, const float* __restrict__ addmat,
    const float* __restrict__ residual, const float* __restrict__ alpha_ptr,
    float scale, int act, int permute)
{
    __shared__ float As[16][132];
    __shared__ float Bs[16][132];

    int z = blockIdx.z;
    int zo = z / zInner, zi = z % zInner;
    const float* Ab = A + zo * sAo + zi * sAi;
    const float* Bb = Bm + zo * sBo + zi * sBi;
    long cOff = zo * sCo + zi * sCi;

    int n0 = blockIdx.x * 128;
    int m0 = blockIdx.y * 128;
    int tid = threadIdx.x;
    int tx = tid & 15, ty = tid >> 4;

    float acc[8][8];
#pragma unroll
    for (int i = 0; i < 8; i++)
#pragma unroll
        for (int j = 0; j < 8; j++) acc[i][j] = 0.f;

    for (int k0 = 0; k0 < K; k0 += 16) {
        // ---- load A tile: 128x16, 512 float4 ----
#pragma unroll
        for (int it = 0; it < 2; it++) {
            int v = tid + it * 256;
            int row = v >> 2, kq = v & 3;
            float4 t = *(const float4*)&Ab[(long)(m0 + row) * K + k0 + kq * 4];
            As[kq * 4 + 0][row] = t.x;
            As[kq * 4 + 1][row] = t.y;
            As[kq * 4 + 2][row] = t.z;
            As[kq * 4 + 3][row] = t.w;
        }
        // ---- load B tile ----
        if (bT) {  // B is [N,K]
#pragma unroll
            for (int it = 0; it < 2; it++) {
                int v = tid + it * 256;
                int row = v >> 2, kq = v & 3;
                float4 t = make_float4(0.f, 0.f, 0.f, 0.f);
                if (n0 + row < N)
                    t = *(const float4*)&Bb[(long)(n0 + row) * K + k0 + kq * 4];
                Bs[kq * 4 + 0][row] = t.x;
                Bs[kq * 4 + 1][row] = t.y;
                Bs[kq * 4 + 2][row] = t.z;
                Bs[kq * 4 + 3][row] = t.w;
            }
        } else {  // B is [K,N]
#pragma unroll
            for (int it = 0; it < 2; it++) {
                int v = tid + it * 256;
                int kr = v >> 5, nq = v & 31;
                float4 t = make_float4(0.f, 0.f, 0.f, 0.f);
                int n = n0 + nq * 4;
                if (n < N)
                    t = *(const float4*)&Bb[(long)(k0 + kr) * N + n];
                *(float4*)&Bs[kr][nq * 4] = t;
            }
        }
        __syncthreads();

#pragma unroll
        for (int kk = 0; kk < 16; kk++) {
            float a[8], b[8];
            *(float4*)&a[0] = *(const float4*)&As[kk][ty * 8];
            *(float4*)&a[4] = *(const float4*)&As[kk][ty * 8 + 4];
            *(float4*)&b[0] = *(const float4*)&Bs[kk][tx * 8];
            *(float4*)&b[4] = *(const float4*)&Bs[kk][tx * 8 + 4];
#pragma unroll
            for (int i = 0; i < 8; i++)
#pragma unroll
                for (int j = 0; j < 8; j++) acc[i][j] += a[i] * b[j];
        }
        __syncthreads();
    }

    float alpha = alpha_ptr ? *alpha_ptr : 1.0f;

#pragma unroll
    for (int i = 0; i < 8; i++) {
        int m = m0 + ty * 8 + i;
#pragma unroll
        for (int j = 0; j < 8; j++) {
            int n = n0 + tx * 8 + j;
            if (n >= N) continue;
            float v = acc[i][j] * scale;
            if (bias) v += bias[n];
            long idx = cOff + (long)m * ldc + n;
            if (addmat) v += addmat[idx];
            if (act == 1) v = fmaxf(v, 0.f);
            else if (act == 2) v = v > 0.f ? v : 0.01f * v;
            if (residual) v = residual[idx] + alpha * v;
            if (permute) {
                // [M,d] -> [B, H, L, hd]
                int bb = m >> 10, l = m & 1023, h = n >> 6, dd = n & 63;
                C[(((long)(bb * NH + h)) * LSEQ + l) * HD + dd] = v;
            } else {
                C[idx] = v;
            }
        }
    }
}

// ---------------------------------------------------------------------------
// Row softmax, in place. One CTA per row, online max/sum then normalize pass.
// ---------------------------------------------------------------------------
__global__ void __launch_bounds__(256) softmax_k(float* __restrict__ data, int ncols)
{
    long row = blockIdx.x;
    float* p = data + row * (long)ncols;
    int tid = threadIdx.x;

    float m = -1e30f, s = 0.f;
    for (int i = tid; i < ncols; i += 256) {
        float v = p[i];
        if (v > m) { s *= __expf(m - v); m = v; }
        s += __expf(v - m);
    }
    __shared__ float sm[256], ss[256];
    sm[tid] = m; ss[tid] = s;
    __syncthreads();
    for (int o = 128; o > 0; o >>= 1) {
        if (tid < o) {
            float m2 = sm[tid + o], s2 = ss[tid + o];
            float mm = fmaxf(sm[tid], m2);
            ss[tid] = ss[tid] * __expf(sm[tid] - mm) + s2 * __expf(m2 - mm);
            sm[tid] = mm;
        }
        __syncthreads();
    }
    float gm = sm[0];
    float inv = 1.0f / ss[0];
    for (int i = tid; i < ncols; i += 256)
        p[i] = __expf(p[i] - gm) * inv;
}

// ---------------------------------------------------------------------------
// Host-side launch helpers
// ---------------------------------------------------------------------------
static void gemm(const float* A, const float* B, float* C,
                 int M, int N, int K, bool bT,
                 int batch = 1,
                 long sAo = 0, long sAi = 0, long sBo = 0, long sBi = 0,
                 long sCo = 0, long sCi = 0, int zInner = 1,
                 int ldc = 0,
                 const float* bias = nullptr, const float* addmat = nullptr,
                 const float* residual = nullptr, const float* alpha = nullptr,
                 float scale = 1.0f, int act = 0, int permute = 0)
{
    if (ldc == 0) ldc = N;
    dim3 grid((N + 127) / 128, (M + 127) / 128, batch);
    gemm_k<<<grid, 256>>>(A, B, C, M, N, K, bT ? 1 : 0,
                          sAo, sAi, sBo, sBi, sCo, sCi, zInner, ldc,
                          bias, addmat, residual, alpha, scale, act, permute);
}

extern "C" void kernel_launch(void* const* d_in, const int* in_sizes, int n_in,
                              void* d_out, int out_size)
{
    const float* tgt   = (const float*)d_in[0];
    const float* src   = (const float*)d_in[1];
    const float* emb   = (const float*)d_in[2];
    const float* va_w  = (const float*)d_in[3];
    const float* va_b  = (const float*)d_in[4];
    const float* a_va  = (const float*)d_in[5];
    const float* sa_wq = (const float*)d_in[6];
    const float* sa_bq = (const float*)d_in[7];
    const float* sa_wk = (const float*)d_in[8];
    const float* sa_bk = (const float*)d_in[9];
    const float* sa_wv = (const float*)d_in[10];
    const float* sa_bv = (const float*)d_in[11];
    const float* sa_wo = (const float*)d_in[12];
    const float* sa_bo = (const float*)d_in[13];
    const float* a_sa  = (const float*)d_in[14];
    const float* ca_wq = (const float*)d_in[15];
    const float* ca_bq = (const float*)d_in[16];
    const float* ca_wk = (const float*)d_in[17];
    const float* ca_bk = (const float*)d_in[18];
    const float* ca_wv = (const float*)d_in[19];
    const float* ca_bv = (const float*)d_in[20];
    const float* ca_wo = (const float*)d_in[21];
    const float* ca_bo = (const float*)d_in[22];
    const float* a_ca  = (const float*)d_in[23];
    const float* ff_w1 = (const float*)d_in[24];
    const float* ff_b1 = (const float*)d_in[25];
    const float* ff_w2 = (const float*)d_in[26];
    const float* ff_b2 = (const float*)d_in[27];
    const float* a_ff  = (const float*)d_in[28];
    float* out = (float*)d_out;

    void* p;
    cudaGetSymbolAddress(&p, g_P);   float* P   = (float*)p;
    cudaGetSymbolAddress(&p, g_A);   float* Av  = (float*)p;
    cudaGetSymbolAddress(&p, g_tmp); float* tmp = (float*)p;
    cudaGetSymbolAddress(&p, g_x1);  float* x1  = (float*)p;
    cudaGetSymbolAddress(&p, g_x2);  float* x2  = (float*)p;
    cudaGetSymbolAddress(&p, g_q);   float* q   = (float*)p;
    cudaGetSymbolAddress(&p, g_k);   float* k   = (float*)p;
    cudaGetSymbolAddress(&p, g_v);   float* v   = (float*)p;
    cudaGetSymbolAddress(&p, g_y);   float* y   = (float*)p;
    cudaGetSymbolAddress(&p, g_h);   float* h   = (float*)p;

    const float inv_sqrt_d = 1.0f / 32.0f;  // 1/sqrt(1024)  (FULL dim, per ref)
    const long sQ = (long)LSEQ * HD;        // per-(b,h) q/k/v stride = 65536
    const long sS = (long)LSEQ * LSEQ;      // per-(b,h) score stride = 1048576

    // ===== Vocabulary attention =====
    // logits = tgt @ emb^T  -> P [4096, 32000]
    gemm(tgt, emb, P, MROWS, VOCAB, DMODEL, /*bT=*/true);
    softmax_k<<<MROWS, 256>>>(P, VOCAB);
    // A = P @ emb  [4096, 1024]
    gemm(P, emb, Av, MROWS, DMODEL, VOCAB, false);
    // tmp = A @ va_w[1024:2048]
    gemm(Av, va_w + (long)DMODEL * DMODEL, tmp, MROWS, DMODEL, DMODEL, false);
    // x1 = tgt + alpha_va * (tgt @ va_w[0:1024] + tmp + va_b)
    gemm(tgt, va_w, x1, MROWS, DMODEL, DMODEL, false, 1, 0,0,0,0,0,0,1, DMODEL,
         va_b, tmp, tgt, a_va);

    // ===== Self attention =====
    gemm(x1, sa_wq, q, MROWS, DMODEL, DMODEL, false, 1, 0,0,0,0,0,0,1, DMODEL,
         sa_bq, nullptr, nullptr, nullptr, 1.f, /*relu*/1, /*permute*/1);
    gemm(x1, sa_wk, k, MROWS, DMODEL, DMODEL, false, 1, 0,0,0,0,0,0,1, DMODEL,
         sa_bk, nullptr, nullptr, nullptr, 1.f, 1, 1);
    gemm(x1, sa_wv, v, MROWS, DMODEL, DMODEL, false, 1, 0,0,0,0,0,0,1, DMODEL,
         sa_bv, nullptr, nullptr, nullptr, 1.f, 1, 1);
    // scores[z] = q_z @ k_z^T / 32   (64 batches)
    gemm(q, k, P, LSEQ, LSEQ, HD, true, NH * 4,
         sQ, 0, sQ, 0, sS, 0, 1, LSEQ,
         nullptr, nullptr, nullptr, nullptr, inv_sqrt_d);
    softmax_k<<<NH * 4 * LSEQ, 256>>>(P, LSEQ);
    // y_z = P_z @ v_z  -> un-permuted [4096, 1024]
    gemm(P, v, y, LSEQ, HD, LSEQ, false, NH * 4,
         sS * NH, sS, sQ * NH, sQ,
         (long)LSEQ * DMODEL, HD, NH, DMODEL);
    // x2 = x1 + alpha_sa * relu(y @ wo + bo)
    gemm(y, sa_wo, x2, MROWS, DMODEL, DMODEL, false, 1, 0,0,0,0,0,0,1, DMODEL,
         sa_bo, nullptr, x1, a_sa, 1.f, 1, 0);

    // ===== Cross attention (q from x2, k/v from src) =====
    gemm(x2, ca_wq, q, MROWS, DMODEL, DMODEL, false, 1, 0,0,0,0,0,0,1, DMODEL,
         ca_bq, nullptr, nullptr, nullptr, 1.f, 1, 1);
    gemm(src, ca_wk, k, MROWS, DMODEL, DMODEL, false, 1, 0,0,0,0,0,0,1, DMODEL,
         ca_bk, nullptr, nullptr, nullptr, 1.f, 1, 1);
    gemm(src, ca_wv, v, MROWS, DMODEL, DMODEL, false, 1, 0,0,0,0,0,0,1, DMODEL,
         ca_bv, nullptr, nullptr, nullptr, 1.f, 1, 1);
    gemm(q, k, P, LSEQ, LSEQ, HD, true, NH * 4,
         sQ, 0, sQ, 0, sS, 0, 1, LSEQ,
         nullptr, nullptr, nullptr, nullptr, inv_sqrt_d);
    softmax_k<<<NH * 4 * LSEQ, 256>>>(P, LSEQ);
    gemm(P, v, y, LSEQ, HD, LSEQ, false, NH * 4,
         sS * NH, sS, sQ * NH, sQ,
         (long)LSEQ * DMODEL, HD, NH, DMODEL);
    // x3 (reuse x1) = x2 + alpha_ca * relu(y @ wo + bo)
    gemm(y, ca_wo, x1, MROWS, DMODEL, DMODEL, false, 1, 0,0,0,0,0,0,1, DMODEL,
         ca_bo, nullptr, x2, a_ca, 1.f, 1, 0);

    // ===== Feed forward =====
    gemm(x1, ff_w1, h, MROWS, DFF, DMODEL, false, 1, 0,0,0,0,0,0,1, DFF,
         ff_b1, nullptr, nullptr, nullptr, 1.f, /*leaky*/2, 0);
    gemm(h, ff_w2, out, MROWS, DMODEL, DFF, false, 1, 0,0,0,0,0,0,1, DMODEL,
         ff_b2, nullptr, x1, a_ff, 1.f, 0, 0);
}

// round 3
// speedup vs baseline: 1.0059x; 1.0059x over previous
#include <cuda_runtime.h>
#include <cuda_bf16.h>
#include <math.h>

// ---------------------------------------------------------------------------
// Problem constants (fixed by the dataset)
//   B=4, L=1024, d=1024, V=32000, NHEAD=16, hd=64, dff=2048, M = B*L = 4096
// ---------------------------------------------------------------------------
#define MROWS 4096
#define DMODEL 1024
#define VOCAB 32000
#define DFF 2048
#define NH 16
#define HD 64
#define LSEQ 1024

// Scratch in device globals (allocation-free rule)
__device__ float g_P[(long)MROWS * VOCAB];      // 524 MB: vocab probs / attn scores
__device__ float g_A[MROWS * DMODEL];
__device__ float g_tmp[MROWS * DMODEL];
__device__ float g_x1[MROWS * DMODEL];
__device__ float g_x2[MROWS * DMODEL];
__device__ float g_q[MROWS * DMODEL];
__device__ float g_k[MROWS * DMODEL];
__device__ float g_v[MROWS * DMODEL];
__device__ float g_y[MROWS * DMODEL];
__device__ float g_h[MROWS * DFF];

// ---------------------------------------------------------------------------
// General tiled SGEMM: C = epilogue( scale * A@B (+bias) (+addmat) )
//   A is [M,K] row-major. B is [K,N] (bT=0) or [N,K] (bT=1), row-major.
//   Batched via blockIdx.z with split offsets: off = (z/zInner)*sXo + (z%zInner)*sXi
//   Epilogue order: v = acc*scale; v += bias[n]; v += addmat[idx]; act(v);
//                   v = residual[idx] + alpha*v;  write (optionally head-permuted)
//   Requirements used here: M % 128 == 0, K % 16 == 0.  N guarded.
// ---------------------------------------------------------------------------
__global__ void __launch_bounds__(256) gemm_k(
    const float* __restrict__ A, const float* __restrict__ Bm, float* __restrict__ C,
    int M, int N, int K, int bT,
    long sAo, long sAi, long sBo, long sBi, long sCo, long sCi, int zInner, int ldc,
    const float* __restrict__ bias, const float* __restrict__ addmat,
    const float* __restrict__ residual, const float* __restrict__ alpha_ptr,
    float scale, int act, int permute)
{
    __shared__ float As[16][132];
    __shared__ float Bs[16][132];

    int z = blockIdx.z;
    int zo = z / zInner, zi = z % zInner;
    const float* Ab = A + zo * sAo + zi * sAi;
    const float* Bb = Bm + zo * sBo + zi * sBi;
    long cOff = zo * sCo + zi * sCi;

    int n0 = blockIdx.x * 128;
    int m0 = blockIdx.y * 128;
    int tid = threadIdx.x;
    int tx = tid & 15, ty = tid >> 4;

    float acc[8][8];
#pragma unroll
    for (int i = 0; i < 8; i++)
#pragma unroll
        for (int j = 0; j < 8; j++) acc[i][j] = 0.f;

    for (int k0 = 0; k0 < K; k0 += 16) {
        // ---- load A tile: 128x16, 512 float4 ----
#pragma unroll
        for (int it = 0; it < 2; it++) {
            int v = tid + it * 256;
            int row = v >> 2, kq = v & 3;
            float4 t = *(const float4*)&Ab[(long)(m0 + row) * K + k0 + kq * 4];
            As[kq * 4 + 0][row] = t.x;
            As[kq * 4 + 1][row] = t.y;
            As[kq * 4 + 2][row] = t.z;
            As[kq * 4 + 3][row] = t.w;
        }
        // ---- load B tile ----
        if (bT) {  // B is [N,K]
#pragma unroll
            for (int it = 0; it < 2; it++) {
                int v = tid + it * 256;
                int row = v >> 2, kq = v & 3;
                float4 t = make_float4(0.f, 0.f, 0.f, 0.f);
                if (n0 + row < N)
                    t = *(const float4*)&Bb[(long)(n0 + row) * K + k0 + kq * 4];
                Bs[kq * 4 + 0][row] = t.x;
                Bs[kq * 4 + 1][row] = t.y;
                Bs[kq * 4 + 2][row] = t.z;
                Bs[kq * 4 + 3][row] = t.w;
            }
        } else {  // B is [K,N]
#pragma unroll
            for (int it = 0; it < 2; it++) {
                int v = tid + it * 256;
                int kr = v >> 5, nq = v & 31;
                float4 t = make_float4(0.f, 0.f, 0.f, 0.f);
                int n = n0 + nq * 4;
                if (n < N)
                    t = *(const float4*)&Bb[(long)(k0 + kr) * N + n];
                *(float4*)&Bs[kr][nq * 4] = t;
            }
        }
        __syncthreads();

#pragma unroll
        for (int kk = 0; kk < 16; kk++) {
            float a[8], b[8];
            *(float4*)&a[0] = *(const float4*)&As[kk][ty * 8];
            *(float4*)&a[4] = *(const float4*)&As[kk][ty * 8 + 4];
            *(float4*)&b[0] = *(const float4*)&Bs[kk][tx * 8];
            *(float4*)&b[4] = *(const float4*)&Bs[kk][tx * 8 + 4];
#pragma unroll
            for (int i = 0; i < 8; i++)
#pragma unroll
                for (int j = 0; j < 8; j++) acc[i][j] += a[i] * b[j];
        }
        __syncthreads();
    }

    float alpha = alpha_ptr ? *alpha_ptr : 1.0f;

#pragma unroll
    for (int i = 0; i < 8; i++) {
        int m = m0 + ty * 8 + i;
#pragma unroll
        for (int j = 0; j < 8; j++) {
            int n = n0 + tx * 8 + j;
            if (n >= N) continue;
            float v = acc[i][j] * scale;
            if (bias) v += bias[n];
            long idx = cOff + (long)m * ldc + n;
            if (addmat) v += addmat[idx];
            if (act == 1) v = fmaxf(v, 0.f);
            else if (act == 2) v = v > 0.f ? v : 0.01f * v;
            if (residual) v = residual[idx] + alpha * v;
            if (permute) {
                // [M,d] -> [B, H, L, hd]
                int bb = m >> 10, l = m & 1023, h = n >> 6, dd = n & 63;
                C[(((long)(bb * NH + h)) * LSEQ + l) * HD + dd] = v;
            } else {
                C[idx] = v;
            }
        }
    }
}

// ---------------------------------------------------------------------------
// Row softmax, in place. One CTA per row, online max/sum then normalize pass.
// ---------------------------------------------------------------------------
__global__ void __launch_bounds__(256) softmax_k(float* __restrict__ data, int ncols)
{
    long row = blockIdx.x;
    float* p = data + row * (long)ncols;
    int tid = threadIdx.x;

    float m = -1e30f, s = 0.f;
    for (int i = tid; i < ncols; i += 256) {
        float v = p[i];
        if (v > m) { s *= __expf(m - v); m = v; }
        s += __expf(v - m);
    }
    __shared__ float sm[256], ss[256];
    sm[tid] = m; ss[tid] = s;
    __syncthreads();
    for (int o = 128; o > 0; o >>= 1) {
        if (tid < o) {
            float m2 = sm[tid + o], s2 = ss[tid + o];
            float mm = fmaxf(sm[tid], m2);
            ss[tid] = ss[tid] * __expf(sm[tid] - mm) + s2 * __expf(m2 - mm);
            sm[tid] = mm;
        }
        __syncthreads();
    }
    float gm = sm[0];
    float inv = 1.0f / ss[0];
    for (int i = tid; i < ncols; i += 256)
        p[i] = __expf(p[i] - gm) * inv;
}

// ---------------------------------------------------------------------------
// Host-side launch helpers
// ---------------------------------------------------------------------------
static void gemm(const float* A, const float* B, float* C,
                 int M, int N, int K, bool bT,
                 int batch = 1,
                 long sAo = 0, long sAi = 0, long sBo = 0, long sBi = 0,
                 long sCo = 0, long sCi = 0, int zInner = 1,
                 int ldc = 0,
                 const float* bias = nullptr, const float* addmat = nullptr,
                 const float* residual = nullptr, const float* alpha = nullptr,
                 float scale = 1.0f, int act = 0, int permute = 0)
{
    if (ldc == 0) ldc = N;
    dim3 grid((N + 127) / 128, (M + 127) / 128, batch);
    gemm_k<<<grid, 256>>>(A, B, C, M, N, K, bT ? 1 : 0,
                          sAo, sAi, sBo, sBi, sCo, sCi, zInner, ldc,
                          bias, addmat, residual, alpha, scale, act, permute);
}

extern "C" void kernel_launch(void* const* d_in, const int* in_sizes, int n_in,
                              void* d_out, int out_size)
{
    const float* tgt   = (const float*)d_in[0];
    const float* src   = (const float*)d_in[1];
    const float* emb   = (const float*)d_in[2];
    const float* va_w  = (const float*)d_in[3];
    const float* va_b  = (const float*)d_in[4];
    const float* a_va  = (const float*)d_in[5];
    const float* sa_wq = (const float*)d_in[6];
    const float* sa_bq = (const float*)d_in[7];
    const float* sa_wk = (const float*)d_in[8];
    const float* sa_bk = (const float*)d_in[9];
    const float* sa_wv = (const float*)d_in[10];
    const float* sa_bv = (const float*)d_in[11];
    const float* sa_wo = (const float*)d_in[12];
    const float* sa_bo = (const float*)d_in[13];
    const float* a_sa  = (const float*)d_in[14];
    const float* ca_wq = (const float*)d_in[15];
    const float* ca_bq = (const float*)d_in[16];
    const float* ca_wk = (const float*)d_in[17];
    const float* ca_bk = (const float*)d_in[18];
    const float* ca_wv = (const float*)d_in[19];
    const float* ca_bv = (const float*)d_in[20];
    const float* ca_wo = (const float*)d_in[21];
    const float* ca_bo = (const float*)d_in[22];
    const float* a_ca  = (const float*)d_in[23];
    const float* ff_w1 = (const float*)d_in[24];
    const float* ff_b1 = (const float*)d_in[25];
    const float* ff_w2 = (const float*)d_in[26];
    const float* ff_b2 = (const float*)d_in[27];
    const float* a_ff  = (const float*)d_in[28];
    float* out = (float*)d_out;

    void* p;
    cudaGetSymbolAddress(&p, g_P);   float* P   = (float*)p;
    cudaGetSymbolAddress(&p, g_A);   float* Av  = (float*)p;
    cudaGetSymbolAddress(&p, g_tmp); float* tmp = (float*)p;
    cudaGetSymbolAddress(&p, g_x1);  float* x1  = (float*)p;
    cudaGetSymbolAddress(&p, g_x2);  float* x2  = (float*)p;
    cudaGetSymbolAddress(&p, g_q);   float* q   = (float*)p;
    cudaGetSymbolAddress(&p, g_k);   float* k   = (float*)p;
    cudaGetSymbolAddress(&p, g_v);   float* v   = (float*)p;
    cudaGetSymbolAddress(&p, g_y);   float* y   = (float*)p;
    cudaGetSymbolAddress(&p, g_h);   float* h   = (float*)p;

    const float inv_sqrt_d = 1.0f / 32.0f;  // 1/sqrt(1024)  (FULL dim, per ref)
    const long sQ = (long)LSEQ * HD;        // per-(b,h) q/k/v stride = 65536
    const long sS = (long)LSEQ * LSEQ;      // per-(b,h) score stride = 1048576

    // ===== Vocabulary attention =====
    // logits = tgt @ emb^T  -> P [4096, 32000]
    gemm(tgt, emb, P, MROWS, VOCAB, DMODEL, /*bT=*/true);
    softmax_k<<<MROWS, 256>>>(P, VOCAB);
    // A = P @ emb  [4096, 1024]
    gemm(P, emb, Av, MROWS, DMODEL, VOCAB, false);
    // tmp = A @ va_w[1024:2048]
    gemm(Av, va_w + (long)DMODEL * DMODEL, tmp, MROWS, DMODEL, DMODEL, false);
    // x1 = tgt + alpha_va * (tgt @ va_w[0:1024] + tmp + va_b)
    gemm(tgt, va_w, x1, MROWS, DMODEL, DMODEL, false, 1, 0,0,0,0,0,0,1, DMODEL,
         va_b, tmp, tgt, a_va);

    // ===== Self attention =====
    gemm(x1, sa_wq, q, MROWS, DMODEL, DMODEL, false, 1, 0,0,0,0,0,0,1, DMODEL,
         sa_bq, nullptr, nullptr, nullptr, 1.f, /*relu*/1, /*permute*/1);
    gemm(x1, sa_wk, k, MROWS, DMODEL, DMODEL, false, 1, 0,0,0,0,0,0,1, DMODEL,
         sa_bk, nullptr, nullptr, nullptr, 1.f, 1, 1);
    gemm(x1, sa_wv, v, MROWS, DMODEL, DMODEL, false, 1, 0,0,0,0,0,0,1, DMODEL,
         sa_bv, nullptr, nullptr, nullptr, 1.f, 1, 1);
    // scores[z] = q_z @ k_z^T / 32   (64 batches)
    gemm(q, k, P, LSEQ, LSEQ, HD, true, NH * 4,
         sQ, 0, sQ, 0, sS, 0, 1, LSEQ,
         nullptr, nullptr, nullptr, nullptr, inv_sqrt_d);
    softmax_k<<<NH * 4 * LSEQ, 256>>>(P, LSEQ);
    // y_z = P_z @ v_z  -> un-permuted [4096, 1024]
    gemm(P, v, y, LSEQ, HD, LSEQ, false, NH * 4,
         sS * NH, sS, sQ * NH, sQ,
         (long)LSEQ * DMODEL, HD, NH, DMODEL);
    // x2 = x1 + alpha_sa * relu(y @ wo + bo)
    gemm(y, sa_wo, x2, MROWS, DMODEL, DMODEL, false, 1, 0,0,0,0,0,0,1, DMODEL,
         sa_bo, nullptr, x1, a_sa, 1.f, 1, 0);

    // ===== Cross attention (q from x2, k/v from src) =====
    gemm(x2, ca_wq, q, MROWS, DMODEL, DMODEL, false, 1, 0,0,0,0,0,0,1, DMODEL,
         ca_bq, nullptr, nullptr, nullptr, 1.f, 1, 1);
    gemm(src, ca_wk, k, MROWS, DMODEL, DMODEL, false, 1, 0,0,0,0,0,0,1, DMODEL,
         ca_bk, nullptr, nullptr, nullptr, 1.f, 1, 1);
    gemm(src, ca_wv, v, MROWS, DMODEL, DMODEL, false, 1, 0,0,0,0,0,0,1, DMODEL,
         ca_bv, nullptr, nullptr, nullptr, 1.f, 1, 1);
    gemm(q, k, P, LSEQ, LSEQ, HD, true, NH * 4,
         sQ, 0, sQ, 0, sS, 0, 1, LSEQ,
         nullptr, nullptr, nullptr, nullptr, inv_sqrt_d);
    softmax_k<<<NH * 4 * LSEQ, 256>>>(P, LSEQ);
    gemm(P, v, y, LSEQ, HD, LSEQ, false, NH * 4,
         sS * NH, sS, sQ * NH, sQ,
         (long)LSEQ * DMODEL, HD, NH, DMODEL);
    // x3 (reuse x1) = x2 + alpha_ca * relu(y @ wo + bo)
    gemm(y, ca_wo, x1, MROWS, DMODEL, DMODEL, false, 1, 0,0,0,0,0,0,1, DMODEL,
         ca_bo, nullptr, x2, a_ca, 1.f, 1, 0);

    // ===== Feed forward =====
    gemm(x1, ff_w1, h, MROWS, DFF, DMODEL, false, 1, 0,0,0,0,0,0,1, DFF,
         ff_b1, nullptr, nullptr, nullptr, 1.f, /*leaky*/2, 0);
    gemm(h, ff_w2, out, MROWS, DMODEL, DFF, false, 1, 0,0,0,0,0,0,1, DMODEL,
         ff_b2, nullptr, x1, a_ff, 1.f, 0, 0);
}

// round 4
// speedup vs baseline: 1.0059x; 1.0001x over previous
#include <cuda_runtime.h>
#include <cuda_bf16.h>
#include <math.h>

// ---------------------------------------------------------------------------
// Problem constants (fixed by the dataset)
//   B=4, L=1024, d=1024, V=32000, NHEAD=16, hd=64, dff=2048, M = B*L = 4096
// ---------------------------------------------------------------------------
#define MROWS 4096
#define DMODEL 1024
#define VOCAB 32000
#define DFF 2048
#define NH 16
#define HD 64
#define LSEQ 1024

// Scratch in device globals (allocation-free rule)
__device__ float g_P[(long)MROWS * VOCAB];      // 524 MB: vocab probs / attn scores
__device__ float g_A[MROWS * DMODEL];
__device__ float g_tmp[MROWS * DMODEL];
__device__ float g_x1[MROWS * DMODEL];
__device__ float g_x2[MROWS * DMODEL];
__device__ float g_q[MROWS * DMODEL];
__device__ float g_k[MROWS * DMODEL];
__device__ float g_v[MROWS * DMODEL];
__device__ float g_y[MROWS * DMODEL];
__device__ float g_h[MROWS * DFF];

// ---------------------------------------------------------------------------
// General tiled SGEMM: C = epilogue( scale * A@B (+bias) (+addmat) )
//   A is [M,K] row-major. B is [K,N] (bT=0) or [N,K] (bT=1), row-major.
//   Batched via blockIdx.z with split offsets: off = (z/zInner)*sXo + (z%zInner)*sXi
//   Epilogue order: v = acc*scale; v += bias[n]; v += addmat[idx]; act(v);
//                   v = residual[idx] + alpha*v;  write (optionally head-permuted)
//   Requirements used here: M % 128 == 0, K % 16 == 0.  N guarded.
// ---------------------------------------------------------------------------
__global__ void __launch_bounds__(256) gemm_k(
    const float* __restrict__ A, const float* __restrict__ Bm, float* __restrict__ C,
    int M, int N, int K, int bT,
    long sAo, long sAi, long sBo, long sBi, long sCo, long sCi, int zInner, int ldc,
    const float* __restrict__ bias, const float* __restrict__ addmat,
    const float* __restrict__ residual, const float* __restrict__ alpha_ptr,
    float scale, int act, int permute)
{
    __shared__ float As[16][132];
    __shared__ float Bs[16][132];

    int z = blockIdx.z;
    int zo = z / zInner, zi = z % zInner;
    const float* Ab = A + zo * sAo + zi * sAi;
    const float* Bb = Bm + zo * sBo + zi * sBi;
    long cOff = zo * sCo + zi * sCi;

    int n0 = blockIdx.x * 128;
    int m0 = blockIdx.y * 128;
    int tid = threadIdx.x;
    int tx = tid & 15, ty = tid >> 4;

    float acc[8][8];
#pragma unroll
    for (int i = 0; i < 8; i++)
#pragma unroll
        for (int j = 0; j < 8; j++) acc[i][j] = 0.f;

    for (int k0 = 0; k0 < K; k0 += 16) {
        // ---- load A tile: 128x16, 512 float4 ----
#pragma unroll
        for (int it = 0; it < 2; it++) {
            int v = tid + it * 256;
            int row = v >> 2, kq = v & 3;
            float4 t = *(const float4*)&Ab[(long)(m0 + row) * K + k0 + kq * 4];
            As[kq * 4 + 0][row] = t.x;
            As[kq * 4 + 1][row] = t.y;
            As[kq * 4 + 2][row] = t.z;
            As[kq * 4 + 3][row] = t.w;
        }
        // ---- load B tile ----
        if (bT) {  // B is [N,K]
#pragma unroll
            for (int it = 0; it < 2; it++) {
                int v = tid + it * 256;
                int row = v >> 2, kq = v & 3;
                float4 t = make_float4(0.f, 0.f, 0.f, 0.f);
                if (n0 + row < N)
                    t = *(const float4*)&Bb[(long)(n0 + row) * K + k0 + kq * 4];
                Bs[kq * 4 + 0][row] = t.x;
                Bs[kq * 4 + 1][row] = t.y;
                Bs[kq * 4 + 2][row] = t.z;
                Bs[kq * 4 + 3][row] = t.w;
            }
        } else {  // B is [K,N]
#pragma unroll
            for (int it = 0; it < 2; it++) {
                int v = tid + it * 256;
                int kr = v >> 5, nq = v & 31;
                float4 t = make_float4(0.f, 0.f, 0.f, 0.f);
                int n = n0 + nq * 4;
                if (n < N)
                    t = *(const float4*)&Bb[(long)(k0 + kr) * N + n];
                *(float4*)&Bs[kr][nq * 4] = t;
            }
        }
        __syncthreads();

#pragma unroll
        for (int kk = 0; kk < 16; kk++) {
            float a[8], b[8];
            *(float4*)&a[0] = *(const float4*)&As[kk][ty * 8];
            *(float4*)&a[4] = *(const float4*)&As[kk][ty * 8 + 4];
            *(float4*)&b[0] = *(const float4*)&Bs[kk][tx * 8];
            *(float4*)&b[4] = *(const float4*)&Bs[kk][tx * 8 + 4];
#pragma unroll
            for (int i = 0; i < 8; i++)
#pragma unroll
                for (int j = 0; j < 8; j++) acc[i][j] += a[i] * b[j];
        }
        __syncthreads();
    }

    float alpha = alpha_ptr ? *alpha_ptr : 1.0f;

#pragma unroll
    for (int i = 0; i < 8; i++) {
        int m = m0 + ty * 8 + i;
#pragma unroll
        for (int j = 0; j < 8; j++) {
            int n = n0 + tx * 8 + j;
            if (n >= N) continue;
            float v = acc[i][j] * scale;
            if (bias) v += bias[n];
            long idx = cOff + (long)m * ldc + n;
            if (addmat) v += addmat[idx];
            if (act == 1) v = fmaxf(v, 0.f);
            else if (act == 2) v = v > 0.f ? v : 0.01f * v;
            if (residual) v = residual[idx] + alpha * v;
            if (permute) {
                // [M,d] -> [B, H, L, hd]
                int bb = m >> 10, l = m & 1023, h = n >> 6, dd = n & 63;
                C[(((long)(bb * NH + h)) * LSEQ + l) * HD + dd] = v;
            } else {
                C[idx] = v;
            }
        }
    }
}

// ---------------------------------------------------------------------------
// Row softmax, in place. One CTA per row, online max/sum then normalize pass.
// ---------------------------------------------------------------------------
__global__ void __launch_bounds__(256) softmax_k(float* __restrict__ data, int ncols)
{
    long row = blockIdx.x;
    float* p = data + row * (long)ncols;
    int tid = threadIdx.x;

    float m = -1e30f, s = 0.f;
    for (int i = tid; i < ncols; i += 256) {
        float v = p[i];
        if (v > m) { s *= __expf(m - v); m = v; }
        s += __expf(v - m);
    }
    __shared__ float sm[256], ss[256];
    sm[tid] = m; ss[tid] = s;
    __syncthreads();
    for (int o = 128; o > 0; o >>= 1) {
        if (tid < o) {
            float m2 = sm[tid + o], s2 = ss[tid + o];
            float mm = fmaxf(sm[tid], m2);
            ss[tid] = ss[tid] * __expf(sm[tid] - mm) + s2 * __expf(m2 - mm);
            sm[tid] = mm;
        }
        __syncthreads();
    }
    float gm = sm[0];
    float inv = 1.0f / ss[0];
    for (int i = tid; i < ncols; i += 256)
        p[i] = __expf(p[i] - gm) * inv;
}

// ---------------------------------------------------------------------------
// Host-side launch helpers
// ---------------------------------------------------------------------------
static void gemm(const float* A, const float* B, float* C,
                 int M, int N, int K, bool bT,
                 int batch = 1,
                 long sAo = 0, long sAi = 0, long sBo = 0, long sBi = 0,
                 long sCo = 0, long sCi = 0, int zInner = 1,
                 int ldc = 0,
                 const float* bias = nullptr, const float* addmat = nullptr,
                 const float* residual = nullptr, const float* alpha = nullptr,
                 float scale = 1.0f, int act = 0, int permute = 0)
{
    if (ldc == 0) ldc = N;
    dim3 grid((N + 127) / 128, (M + 127) / 128, batch);
    gemm_k<<<grid, 256>>>(A, B, C, M, N, K, bT ? 1 : 0,
                          sAo, sAi, sBo, sBi, sCo, sCi, zInner, ldc,
                          bias, addmat, residual, alpha, scale, act, permute);
}

extern "C" void kernel_launch(void* const* d_in, const int* in_sizes, int n_in,
                              void* d_out, int out_size)
{
    const float* tgt   = (const float*)d_in[0];
    const float* src   = (const float*)d_in[1];
    const float* emb   = (const float*)d_in[2];
    const float* va_w  = (const float*)d_in[3];
    const float* va_b  = (const float*)d_in[4];
    const float* a_va  = (const float*)d_in[5];
    const float* sa_wq = (const float*)d_in[6];
    const float* sa_bq = (const float*)d_in[7];
    const float* sa_wk = (const float*)d_in[8];
    const float* sa_bk = (const float*)d_in[9];
    const float* sa_wv = (const float*)d_in[10];
    const float* sa_bv = (const float*)d_in[11];
    const float* sa_wo = (const float*)d_in[12];
    const float* sa_bo = (const float*)d_in[13];
    const float* a_sa  = (const float*)d_in[14];
    const float* ca_wq = (const float*)d_in[15];
    const float* ca_bq = (const float*)d_in[16];
    const float* ca_wk = (const float*)d_in[17];
    const float* ca_bk = (const float*)d_in[18];
    const float* ca_wv = (const float*)d_in[19];
    const float* ca_bv = (const float*)d_in[20];
    const float* ca_wo = (const float*)d_in[21];
    const float* ca_bo = (const float*)d_in[22];
    const float* a_ca  = (const float*)d_in[23];
    const float* ff_w1 = (const float*)d_in[24];
    const float* ff_b1 = (const float*)d_in[25];
    const float* ff_w2 = (const float*)d_in[26];
    const float* ff_b2 = (const float*)d_in[27];
    const float* a_ff  = (const float*)d_in[28];
    float* out = (float*)d_out;

    void* p;
    cudaGetSymbolAddress(&p, g_P);   float* P   = (float*)p;
    cudaGetSymbolAddress(&p, g_A);   float* Av  = (float*)p;
    cudaGetSymbolAddress(&p, g_tmp); float* tmp = (float*)p;
    cudaGetSymbolAddress(&p, g_x1);  float* x1  = (float*)p;
    cudaGetSymbolAddress(&p, g_x2);  float* x2  = (float*)p;
    cudaGetSymbolAddress(&p, g_q);   float* q   = (float*)p;
    cudaGetSymbolAddress(&p, g_k);   float* k   = (float*)p;
    cudaGetSymbolAddress(&p, g_v);   float* v   = (float*)p;
    cudaGetSymbolAddress(&p, g_y);   float* y   = (float*)p;
    cudaGetSymbolAddress(&p, g_h);   float* h   = (float*)p;

    const float inv_sqrt_d = 1.0f / 32.0f;  // 1/sqrt(1024)  (FULL dim, per ref)
    const long sQ = (long)LSEQ * HD;        // per-(b,h) q/k/v stride = 65536
    const long sS = (long)LSEQ * LSEQ;      // per-(b,h) score stride = 1048576

    // ===== Vocabulary attention =====
    // logits = tgt @ emb^T  -> P [4096, 32000]
    gemm(tgt, emb, P, MROWS, VOCAB, DMODEL, /*bT=*/true);
    softmax_k<<<MROWS, 256>>>(P, VOCAB);
    // A = P @ emb  [4096, 1024]
    gemm(P, emb, Av, MROWS, DMODEL, VOCAB, false);
    // tmp = A @ va_w[1024:2048]
    gemm(Av, va_w + (long)DMODEL * DMODEL, tmp, MROWS, DMODEL, DMODEL, false);
    // x1 = tgt + alpha_va * (tgt @ va_w[0:1024] + tmp + va_b)
    gemm(tgt, va_w, x1, MROWS, DMODEL, DMODEL, false, 1, 0,0,0,0,0,0,1, DMODEL,
         va_b, tmp, tgt, a_va);

    // ===== Self attention =====
    gemm(x1, sa_wq, q, MROWS, DMODEL, DMODEL, false, 1, 0,0,0,0,0,0,1, DMODEL,
         sa_bq, nullptr, nullptr, nullptr, 1.f, /*relu*/1, /*permute*/1);
    gemm(x1, sa_wk, k, MROWS, DMODEL, DMODEL, false, 1, 0,0,0,0,0,0,1, DMODEL,
         sa_bk, nullptr, nullptr, nullptr, 1.f, 1, 1);
    gemm(x1, sa_wv, v, MROWS, DMODEL, DMODEL, false, 1, 0,0,0,0,0,0,1, DMODEL,
         sa_bv, nullptr, nullptr, nullptr, 1.f, 1, 1);
    // scores[z] = q_z @ k_z^T / 32   (64 batches)
    gemm(q, k, P, LSEQ, LSEQ, HD, true, NH * 4,
         sQ, 0, sQ, 0, sS, 0, 1, LSEQ,
         nullptr, nullptr, nullptr, nullptr, inv_sqrt_d);
    softmax_k<<<NH * 4 * LSEQ, 256>>>(P, LSEQ);
    // y_z = P_z @ v_z  -> un-permuted [4096, 1024]
    gemm(P, v, y, LSEQ, HD, LSEQ, false, NH * 4,
         sS * NH, sS, sQ * NH, sQ,
         (long)LSEQ * DMODEL, HD, NH, DMODEL);
    // x2 = x1 + alpha_sa * relu(y @ wo + bo)
    gemm(y, sa_wo, x2, MROWS, DMODEL, DMODEL, false, 1, 0,0,0,0,0,0,1, DMODEL,
         sa_bo, nullptr, x1, a_sa, 1.f, 1, 0);

    // ===== Cross attention (q from x2, k/v from src) =====
    gemm(x2, ca_wq, q, MROWS, DMODEL, DMODEL, false, 1, 0,0,0,0,0,0,1, DMODEL,
         ca_bq, nullptr, nullptr, nullptr, 1.f, 1, 1);
    gemm(src, ca_wk, k, MROWS, DMODEL, DMODEL, false, 1, 0,0,0,0,0,0,1, DMODEL,
         ca_bk, nullptr, nullptr, nullptr, 1.f, 1, 1);
    gemm(src, ca_wv, v, MROWS, DMODEL, DMODEL, false, 1, 0,0,0,0,0,0,1, DMODEL,
         ca_bv, nullptr, nullptr, nullptr, 1.f, 1, 1);
    gemm(q, k, P, LSEQ, LSEQ, HD, true, NH * 4,
         sQ, 0, sQ, 0, sS, 0, 1, LSEQ,
         nullptr, nullptr, nullptr, nullptr, inv_sqrt_d);
    softmax_k<<<NH * 4 * LSEQ, 256>>>(P, LSEQ);
    gemm(P, v, y, LSEQ, HD, LSEQ, false, NH * 4,
         sS * NH, sS, sQ * NH, sQ,
         (long)LSEQ * DMODEL, HD, NH, DMODEL);
    // x3 (reuse x1) = x2 + alpha_ca * relu(y @ wo + bo)
    gemm(y, ca_wo, x1, MROWS, DMODEL, DMODEL, false, 1, 0,0,0,0,0,0,1, DMODEL,
         ca_bo, nullptr, x2, a_ca, 1.f, 1, 0);

    // ===== Feed forward =====
    gemm(x1, ff_w1, h, MROWS, DFF, DMODEL, false, 1, 0,0,0,0,0,0,1, DFF,
         ff_b1, nullptr, nullptr, nullptr, 1.f, /*leaky*/2, 0);
    gemm(h, ff_w2, out, MROWS, DMODEL, DFF, false, 1, 0,0,0,0,0,0,1, DMODEL,
         ff_b2, nullptr, x1, a_ff, 1.f, 0, 0);
}

// round 6
// speedup vs baseline: 7.7309x; 7.6853x over previous
#include <cuda_runtime.h>
#include <cuda_bf16.h>
#include <cstdint>
#include <math.h>

#define MROWS 4096
#define DMODEL 1024
#define VOCAB 32000
#define DFF 2048
#define MD ((size_t)MROWS * DMODEL)

// ---------------- scratch (allocation-free rule) ----------------
__device__ float g_P[(size_t)MROWS * VOCAB];
__device__ float g_tmp[MD], g_x1[MD], g_x2[MD];
__device__ float g_rs[65536];
__device__ __nv_bfloat16 g_Pb[(size_t)MROWS * VOCAB];
__device__ __nv_bfloat16 g_eb[(size_t)VOCAB * DMODEL];
__device__ __nv_bfloat16 g_ebT[(size_t)VOCAB * DMODEL];
__device__ __nv_bfloat16 g_tgtb[MD], g_srcb[MD], g_avb[MD], g_x1b[MD], g_x2b[MD];
__device__ __nv_bfloat16 g_qb[MD], g_kb[MD], g_vtb[MD], g_yb[MD];
__device__ __nv_bfloat16 g_hb[(size_t)MROWS * DFF];
__device__ __nv_bfloat16 g_vawT[(size_t)2 * DMODEL * DMODEL];
__device__ __nv_bfloat16 g_wT[8][(size_t)DMODEL * DMODEL];
__device__ __nv_bfloat16 g_f1T[(size_t)DFF * DMODEL];
__device__ __nv_bfloat16 g_f2T[(size_t)DFF * DMODEL];

// ---------------- PTX helpers (baseline sm_103-safe: HMMA/ldmatrix/cp.async) --
__device__ __forceinline__ uint32_t smem_u32(const void* p) {
    uint32_t a;
    asm("{ .reg .u64 t; cvta.to.shared.u64 t, %1; cvt.u32.u64 %0, t; }" : "=r"(a) : "l"(p));
    return a;
}
#define CP_ASYNC16(dst, src) \
    asm volatile("cp.async.cg.shared.global [%0], [%1], 16;" \
                 :: "r"(dst), "l"(__cvta_generic_to_global(src)) : "memory")
#define CP_COMMIT() asm volatile("cp.async.commit_group;" ::: "memory")
#define CP_WAIT1()  asm volatile("cp.async.wait_group 1;" ::: "memory")
#define LDSM4(r0, r1, r2, r3, a) \
    asm volatile("ldmatrix.sync.aligned.m8n8.x4.shared.b16 {%0,%1,%2,%3}, [%4];" \
                 : "=r"(r0), "=r"(r1), "=r"(r2), "=r"(r3) : "r"(a))
#define MMA16816(c, a, b) \
    asm volatile("mma.sync.aligned.m16n8k16.row.col.f32.bf16.bf16.f32 " \
                 "{%0,%1,%2,%3}, {%4,%5,%6,%7}, {%8,%9}, {%0,%1,%2,%3};" \
                 : "+f"((c)[0]), "+f"((c)[1]), "+f"((c)[2]), "+f"((c)[3]) \
                 : "r"((a)[0]), "r"((a)[1]), "r"((a)[2]), "r"((a)[3]), \
                   "r"((b)[0]), "r"((b)[1]))

// ---------------- bf16 tensor-core GEMM: C[m][n] = epi(sum_k A[m][k]*B[n][k]) --
// A [.,K] row-major bf16 (lda), B [.,K] row-major bf16 (ldb). Block 128 x NT,
// K-chunk 32, 8 warps (4M x 2N), warp tile 32 x NT/2. cp.async double-buffered.
struct GP {
    const __nv_bfloat16 *A, *B;
    float* Cf; __nv_bfloat16* Cb;
    int K, lda, ldb, ldc, Mrows, zInner, act, perm;
    long sAo, sAi, sBo, sBi, sCo, sCi;
    const float *bias, *add, *res, *alpha, *rowScale;
    float scale;
};

template <int NT>
__global__ void __launch_bounds__(256) tgemm_k(GP g)
{
    constexpr int NSUB = NT / 16;           // n8 subtiles per warp
    __shared__ __align__(128) uint8_t smA[2][128 * 64];
    __shared__ __align__(128) uint8_t smB[2][NT * 64];
    const uint32_t smA_u = smem_u32(smA);
    const uint32_t smB_u = smem_u32(smB);

    int tid = threadIdx.x, wid = tid >> 5, lid = tid & 31;
    int wm = wid & 3, wn = wid >> 2;
    int z = blockIdx.z, zo = z / g.zInner, zi = z - zo * g.zInner;
    const __nv_bfloat16* Ab = g.A + zo * g.sAo + zi * g.sAi + (long)blockIdx.x * 128 * g.lda;
    const __nv_bfloat16* Bb = g.B + zo * g.sBo + zi * g.sBi + (long)blockIdx.y * NT * g.ldb;
    long cOff = zo * g.sCo + zi * g.sCi;
    int m0 = blockIdx.x * 128, n0 = blockIdx.y * NT;

    float c[2][NSUB][4];
#pragma unroll
    for (int mt = 0; mt < 2; mt++)
#pragma unroll
        for (int s = 0; s < NSUB; s++)
#pragma unroll
            for (int q = 0; q < 4; q++) c[mt][s][q] = 0.f;

    const int nch = g.K >> 5;

    // chunk loader (32 K-elements = 64B per row, 16B segs, swizzle seg^((row>>1)&3))
    auto issue = [&](int kc) {
        int kb = kc << 5, buf = kc & 1;
#pragma unroll
        for (int it = 0; it < 2; it++) {
            int s2 = tid + (it << 8);
            int row = s2 >> 2, seg = s2 & 3;
            uint32_t d = smA_u + buf * 8192 + (((row << 2) + (seg ^ ((row >> 1) & 3))) << 4);
            CP_ASYNC16(d, Ab + (long)row * g.lda + kb + (seg << 3));
        }
#pragma unroll
        for (int it = 0; it < NT / 64; it++) {
            int s2 = tid + (it << 8);
            int row = s2 >> 2, seg = s2 & 3;
            uint32_t d = smB_u + buf * (NT * 64) + (((row << 2) + (seg ^ ((row >> 1) & 3))) << 4);
            CP_ASYNC16(d, Bb + (long)row * g.ldb + kb + (seg << 3));
        }
    };

    issue(0);
    CP_COMMIT();

    int mi = lid >> 3, j = lid & 7;
    for (int kc = 0; kc < nch; kc++) {
        if (kc + 1 < nch) issue(kc + 1);
        CP_COMMIT();
        CP_WAIT1();
        __syncthreads();

        int buf = kc & 1;
        uint32_t Abase = smA_u + buf * 8192;
        uint32_t Bbase = smB_u + buf * (NT * 64);
#pragma unroll
        for (int ks = 0; ks < 2; ks++) {
            uint32_t aF[2][4];
#pragma unroll
            for (int mt = 0; mt < 2; mt++) {
                int arow = wm * 32 + mt * 16 + ((mi & 1) << 3) + j;
                int aseg = (ks << 1) + (mi >> 1);
                uint32_t ad = Abase + (((arow << 2) + (aseg ^ ((arow >> 1) & 3))) << 4);
                LDSM4(aF[mt][0], aF[mt][1], aF[mt][2], aF[mt][3], ad);
            }
            uint32_t bF[NSUB][2];
#pragma unroll
            for (int gi = 0; gi < NT / 32; gi++) {
                int nrow = wn * (NT / 2) + gi * 16 + ((mi >> 1) << 3) + j;
                int bseg = (ks << 1) + (mi & 1);
                uint32_t bd = Bbase + (((nrow << 2) + (bseg ^ ((nrow >> 1) & 3))) << 4);
                uint32_t r0, r1, r2, r3;
                LDSM4(r0, r1, r2, r3, bd);
                bF[2 * gi][0] = r0; bF[2 * gi][1] = r1;
                bF[2 * gi + 1][0] = r2; bF[2 * gi + 1][1] = r3;
            }
#pragma unroll
            for (int mt = 0; mt < 2; mt++)
#pragma unroll
                for (int s = 0; s < NSUB; s++)
                    MMA16816(c[mt][s], aF[mt], bF[s]);
        }
        __syncthreads();
    }

    // ---- epilogue ----
    float alpha = g.alpha ? *g.alpha : 1.0f;
#pragma unroll
    for (int mt = 0; mt < 2; mt++) {
#pragma unroll
        for (int s = 0; s < NSUB; s++) {
            int rA = m0 + wm * 32 + mt * 16 + (lid >> 2);
            int nn = n0 + wn * (NT / 2) + s * 8 + ((lid & 3) << 1);
#pragma unroll
            for (int hh = 0; hh < 2; hh++) {
                int r = rA + hh * 8;
                float sc = g.scale * (g.rowScale ? g.rowScale[(long)z * g.Mrows + r] : 1.f);
                long rowbase = cOff + (long)r * g.ldc;
#pragma unroll
                for (int w = 0; w < 2; w++) {
                    int n = nn + w;
                    float v = c[mt][s][hh * 2 + w] * sc;
                    if (g.bias) v += __ldg(g.bias + n);
                    long idx = rowbase + n;
                    if (g.add) v += g.add[idx];
                    if (g.act == 1) v = fmaxf(v, 0.f);
                    else if (g.act == 2) v = v > 0.f ? v : 0.01f * v;
                    if (g.res) v = g.res[idx] + alpha * v;
                    if (g.Cf) g.Cf[idx] = v;
                    if (g.Cb) {
                        long bi;
                        if (g.perm == 0) bi = idx;
                        else {
                            int bb = r >> 10, l = r & 1023, h = n >> 6, dd = n & 63;
                            long bh = (bb << 4) + h;
                            bi = (g.perm == 1) ? ((bh << 10) + l) * 64 + dd
                                               : ((bh << 6) + dd) * 1024 + l;
                        }
                        g.Cb[bi] = __float2bfloat16(v);
                    }
                }
            }
        }
    }
}

// ---------------- softmax: fp32 in -> unnormalized bf16 exp + 1/rowsum -------
__device__ __forceinline__ float fexp(float x) {
    float t = fmaxf(x * 1.4426950408889634f, -126.0f);
    int i = __float2int_rd(t);
    float f = t - (float)i;
    float p = 1.f + f * (0.69314718f + f * (0.24022651f + f * (0.05550411f +
              f * (0.00961812f + f * 0.00133336f))));
    return __int_as_float((i + 127) << 23) * p;
}

__global__ void __launch_bounds__(256) softmax_bf_k(
    const float* __restrict__ in, __nv_bfloat16* __restrict__ out,
    float* __restrict__ invsum, int ncols)
{
    long row = blockIdx.x;
    const float4* p = (const float4*)(in + row * (long)ncols);
    uint2* o = (uint2*)(out + row * (long)ncols);
    int nq = ncols >> 2, tid = threadIdx.x;
    __shared__ float red[256];

    float m = -1e30f;
    for (int i = tid; i < nq; i += 256) {
        float4 v = p[i];
        m = fmaxf(m, fmaxf(fmaxf(v.x, v.y), fmaxf(v.z, v.w)));
    }
    red[tid] = m; __syncthreads();
    for (int o2 = 128; o2; o2 >>= 1) {
        if (tid < o2) red[tid] = fmaxf(red[tid], red[tid + o2]);
        __syncthreads();
    }
    m = red[0]; __syncthreads();

    float s = 0.f;
    for (int i = tid; i < nq; i += 256) {
        float4 v = p[i];
        float e0 = fexp(v.x - m), e1 = fexp(v.y - m);
        float e2 = fexp(v.z - m), e3 = fexp(v.w - m);
        s += (e0 + e1) + (e2 + e3);
        __nv_bfloat162 lo = __floats2bfloat162_rn(e0, e1);
        __nv_bfloat162 hi = __floats2bfloat162_rn(e2, e3);
        uint2 u; u.x = *(uint32_t*)&lo; u.y = *(uint32_t*)&hi;
        o[i] = u;
    }
    red[tid] = s; __syncthreads();
    for (int o2 = 128; o2; o2 >>= 1) {
        if (tid < o2) red[tid] += red[tid + o2];
        __syncthreads();
    }
    if (tid == 0) invsum[row] = 1.0f / red[0];
}

// ---------------- conversions ----------------
__global__ void __launch_bounds__(256) conv_k(const float* __restrict__ s,
                                              __nv_bfloat16* __restrict__ d, long n)
{
    long i = ((long)blockIdx.x * 256 + threadIdx.x) << 2;
    if (i < n) {
        float4 v = *(const float4*)(s + i);
        __nv_bfloat162 lo = __floats2bfloat162_rn(v.x, v.y);
        __nv_bfloat162 hi = __floats2bfloat162_rn(v.z, v.w);
        uint2 u; u.x = *(uint32_t*)&lo; u.y = *(uint32_t*)&hi;
        *(uint2*)(d + i) = u;
    }
}
__global__ void convT_k(const float* __restrict__ s, __nv_bfloat16* __restrict__ d,
                        int R, int C)
{
    __shared__ float t[32][33];
    int c0 = blockIdx.x << 5, r0 = blockIdx.y << 5;
    int x = threadIdx.x, y = threadIdx.y;
#pragma unroll
    for (int i = 0; i < 32; i += 8)
        t[y + i][x] = s[(long)(r0 + y + i) * C + c0 + x];
    __syncthreads();
#pragma unroll
    for (int i = 0; i < 32; i += 8)
        d[(long)(c0 + y + i) * R + r0 + x] = __float2bfloat16(t[x][y + i]);
}

// ---------------- host helpers ----------------
static void conv(const float* s, __nv_bfloat16* d, long n) {
    conv_k<<<(unsigned)((n / 4 + 255) / 256), 256>>>(s, d, n);
}
static void convT(const float* s, __nv_bfloat16* d, int R, int C) {
    convT_k<<<dim3(C / 32, R / 32), dim3(32, 8)>>>(s, d, R, C);
}

static void tg(const __nv_bfloat16* A, const __nv_bfloat16* B, float* Cf, __nv_bfloat16* Cb,
               int Mtiles, int Ntot, int K, int lda, int ldb, int ldc, int NT,
               int batch = 1,
               long sAo = 0, long sAi = 0, long sBo = 0, long sBi = 0,
               long sCo = 0, long sCi = 0, int zInner = 1,
               const float* bias = nullptr, const float* add = nullptr,
               const float* res = nullptr, const float* alpha = nullptr,
               const float* rowScale = nullptr, float scale = 1.0f,
               int act = 0, int perm = 0)
{
    GP g;
    g.A = A; g.B = B; g.Cf = Cf; g.Cb = Cb;
    g.K = K; g.lda = lda; g.ldb = ldb; g.ldc = ldc;
    g.Mrows = Mtiles * 128; g.zInner = zInner; g.act = act; g.perm = perm;
    g.sAo = sAo; g.sAi = sAi; g.sBo = sBo; g.sBi = sBi; g.sCo = sCo; g.sCi = sCi;
    g.bias = bias; g.add = add; g.res = res; g.alpha = alpha; g.rowScale = rowScale;
    g.scale = scale;
    dim3 grid(Mtiles, Ntot / NT, batch);
    if (NT == 128) tgemm_k<128><<<grid, 256>>>(g);
    else           tgemm_k<64><<<grid, 256>>>(g);
}

extern "C" void kernel_launch(void* const* d_in, const int* in_sizes, int n_in,
                              void* d_out, int out_size)
{
    const float* tgt   = (const float*)d_in[0];
    const float* src   = (const float*)d_in[1];
    const float* emb   = (const float*)d_in[2];
    const float* va_w  = (const float*)d_in[3];
    const float* va_b  = (const float*)d_in[4];
    const float* a_va  = (const float*)d_in[5];
    const float* sa_wq = (const float*)d_in[6];
    const float* sa_bq = (const float*)d_in[7];
    const float* sa_wk = (const float*)d_in[8];
    const float* sa_bk = (const float*)d_in[9];
    const float* sa_wv = (const float*)d_in[10];
    const float* sa_bv = (const float*)d_in[11];
    const float* sa_wo = (const float*)d_in[12];
    const float* sa_bo = (const float*)d_in[13];
    const float* a_sa  = (const float*)d_in[14];
    const float* ca_wq = (const float*)d_in[15];
    const float* ca_bq = (const float*)d_in[16];
    const float* ca_wk = (const float*)d_in[17];
    const float* ca_bk = (const float*)d_in[18];
    const float* ca_wv = (const float*)d_in[19];
    const float* ca_bv = (const float*)d_in[20];
    const float* ca_wo = (const float*)d_in[21];
    const float* ca_bo = (const float*)d_in[22];
    const float* a_ca  = (const float*)d_in[23];
    const float* ff_w1 = (const float*)d_in[24];
    const float* ff_b1 = (const float*)d_in[25];
    const float* ff_w2 = (const float*)d_in[26];
    const float* ff_b2 = (const float*)d_in[27];
    const float* a_ff  = (const float*)d_in[28];
    float* out = (float*)d_out;

    void* p;
    cudaGetSymbolAddress(&p, g_P);    float* P    = (float*)p;
    cudaGetSymbolAddress(&p, g_tmp);  float* tmp  = (float*)p;
    cudaGetSymbolAddress(&p, g_x1);   float* x1   = (float*)p;
    cudaGetSymbolAddress(&p, g_x2);   float* x2   = (float*)p;
    cudaGetSymbolAddress(&p, g_rs);   float* rs   = (float*)p;
    cudaGetSymbolAddress(&p, g_Pb);   __nv_bfloat16* Pb   = (__nv_bfloat16*)p;
    cudaGetSymbolAddress(&p, g_eb);   __nv_bfloat16* eb   = (__nv_bfloat16*)p;
    cudaGetSymbolAddress(&p, g_ebT);  __nv_bfloat16* ebT  = (__nv_bfloat16*)p;
    cudaGetSymbolAddress(&p, g_tgtb); __nv_bfloat16* tgtb = (__nv_bfloat16*)p;
    cudaGetSymbolAddress(&p, g_srcb); __nv_bfloat16* srcb = (__nv_bfloat16*)p;
    cudaGetSymbolAddress(&p, g_avb);  __nv_bfloat16* avb  = (__nv_bfloat16*)p;
    cudaGetSymbolAddress(&p, g_x1b);  __nv_bfloat16* x1b  = (__nv_bfloat16*)p;
    cudaGetSymbolAddress(&p, g_x2b);  __nv_bfloat16* x2b  = (__nv_bfloat16*)p;
    cudaGetSymbolAddress(&p, g_qb);   __nv_bfloat16* qb   = (__nv_bfloat16*)p;
    cudaGetSymbolAddress(&p, g_kb);   __nv_bfloat16* kb   = (__nv_bfloat16*)p;
    cudaGetSymbolAddress(&p, g_vtb);  __nv_bfloat16* vtb  = (__nv_bfloat16*)p;
    cudaGetSymbolAddress(&p, g_yb);   __nv_bfloat16* yb   = (__nv_bfloat16*)p;
    cudaGetSymbolAddress(&p, g_hb);   __nv_bfloat16* hb   = (__nv_bfloat16*)p;
    cudaGetSymbolAddress(&p, g_vawT); __nv_bfloat16* vawT = (__nv_bfloat16*)p;
    cudaGetSymbolAddress(&p, g_wT);   __nv_bfloat16* wT   = (__nv_bfloat16*)p;
    cudaGetSymbolAddress(&p, g_f1T);  __nv_bfloat16* f1T  = (__nv_bfloat16*)p;
    cudaGetSymbolAddress(&p, g_f2T);  __nv_bfloat16* f2T  = (__nv_bfloat16*)p;
    const size_t WSZ = (size_t)DMODEL * DMODEL;

    conv(emb, eb, (long)VOCAB * DMODEL);
    convT(emb, ebT, VOCAB, DMODEL);
    conv(tgt, tgtb, (long)MD);
    conv(src, srcb, (long)MD);
    convT(va_w,  vawT,         2 * DMODEL, DMODEL);
    convT(sa_wq, wT + 0 * WSZ, DMODEL, DMODEL);
    convT(sa_wk, wT + 1 * WSZ, DMODEL, DMODEL);
    convT(sa_wv, wT + 2 * WSZ, DMODEL, DMODEL);
    convT(sa_wo, wT + 3 * WSZ, DMODEL, DMODEL);
    convT(ca_wq, wT + 4 * WSZ, DMODEL, DMODEL);
    convT(ca_wk, wT + 5 * WSZ, DMODEL, DMODEL);
    convT(ca_wv, wT + 6 * WSZ, DMODEL, DMODEL);
    convT(ca_wo, wT + 7 * WSZ, DMODEL, DMODEL);
    convT(ff_w1, f1T, DMODEL, DFF);
    convT(ff_w2, f2T, DFF, DMODEL);

    const float inv_sd = 1.0f / 32.0f;
    const long sQ = 65536, sS = 1048576;

    // ===== Vocabulary attention =====
    tg(tgtb, eb, P, nullptr, 32, VOCAB, DMODEL, DMODEL, DMODEL, VOCAB, 128);
    softmax_bf_k<<<MROWS, 256>>>(P, Pb, rs, VOCAB);
    tg(Pb, ebT, nullptr, avb, 32, DMODEL, VOCAB, VOCAB, VOCAB, DMODEL, 128,
       1, 0,0,0,0,0,0,1, nullptr, nullptr, nullptr, nullptr, rs);
    tg(avb, vawT + DMODEL, tmp, nullptr, 32, DMODEL, DMODEL, DMODEL, 2 * DMODEL, DMODEL, 128);
    tg(tgtb, vawT, x1, x1b, 32, DMODEL, DMODEL, DMODEL, 2 * DMODEL, DMODEL, 128,
       1, 0,0,0,0,0,0,1, va_b, tmp, tgt, a_va);

    // ===== Self attention =====
    tg(x1b, wT + 0 * WSZ, nullptr, qb, 32, DMODEL, DMODEL, DMODEL, DMODEL, DMODEL, 128,
       1, 0,0,0,0,0,0,1, sa_bq, nullptr, nullptr, nullptr, nullptr, 1.f, 1, 1);
    tg(x1b, wT + 1 * WSZ, nullptr, kb, 32, DMODEL, DMODEL, DMODEL, DMODEL, DMODEL, 128,
       1, 0,0,0,0,0,0,1, sa_bk, nullptr, nullptr, nullptr, nullptr, 1.f, 1, 1);
    tg(x1b, wT + 2 * WSZ, nullptr, vtb, 32, DMODEL, DMODEL, DMODEL, DMODEL, DMODEL, 128,
       1, 0,0,0,0,0,0,1, sa_bv, nullptr, nullptr, nullptr, nullptr, 1.f, 1, 2);
    tg(qb, kb, P, nullptr, 8, 1024, 64, 64, 64, 1024, 128,
       64, sQ, 0, sQ, 0, sS, 0, 1,
       nullptr, nullptr, nullptr, nullptr, nullptr, inv_sd);
    softmax_bf_k<<<65536, 256>>>(P, Pb, rs, 1024);
    tg(Pb, vtb, nullptr, yb, 8, 64, 1024, 1024, 1024, DMODEL, 64,
       64, 16L * sS, sS, 16L * sQ, sQ, (long)1024 * DMODEL, 64, 16,
       nullptr, nullptr, nullptr, nullptr, rs);
    tg(yb, wT + 3 * WSZ, x2, x2b, 32, DMODEL, DMODEL, DMODEL, DMODEL, DMODEL, 128,
       1, 0,0,0,0,0,0,1, sa_bo, nullptr, x1, a_sa, nullptr, 1.f, 1, 0);

    // ===== Cross attention =====
    tg(x2b, wT + 4 * WSZ, nullptr, qb, 32, DMODEL, DMODEL, DMODEL, DMODEL, DMODEL, 128,
       1, 0,0,0,0,0,0,1, ca_bq, nullptr, nullptr, nullptr, nullptr, 1.f, 1, 1);
    tg(srcb, wT + 5 * WSZ, nullptr, kb, 32, DMODEL, DMODEL, DMODEL, DMODEL, DMODEL, 128,
       1, 0,0,0,0,0,0,1, ca_bk, nullptr, nullptr, nullptr, nullptr, 1.f, 1, 1);
    tg(srcb, wT + 6 * WSZ, nullptr, vtb, 32, DMODEL, DMODEL, DMODEL, DMODEL, DMODEL, 128,
       1, 0,0,0,0,0,0,1, ca_bv, nullptr, nullptr, nullptr, nullptr, 1.f, 1, 2);
    tg(qb, kb, P, nullptr, 8, 1024, 64, 64, 64, 1024, 128,
       64, sQ, 0, sQ, 0, sS, 0, 1,
       nullptr, nullptr, nullptr, nullptr, nullptr, inv_sd);
    softmax_bf_k<<<65536, 256>>>(P, Pb, rs, 1024);
    tg(Pb, vtb, nullptr, yb, 8, 64, 1024, 1024, 1024, DMODEL, 64,
       64, 16L * sS, sS, 16L * sQ, sQ, (long)1024 * DMODEL, 64, 16,
       nullptr, nullptr, nullptr, nullptr, rs);
    tg(yb, wT + 7 * WSZ, x1, x1b, 32, DMODEL, DMODEL, DMODEL, DMODEL, DMODEL, 128,
       1, 0,0,0,0,0,0,1, ca_bo, nullptr, x2, a_ca, nullptr, 1.f, 1, 0);

    // ===== Feed forward =====
    tg(x1b, f1T, nullptr, hb, 32, DFF, DMODEL, DMODEL, DMODEL, DFF, 128,
       1, 0,0,0,0,0,0,1, ff_b1, nullptr, nullptr, nullptr, nullptr, 1.f, 2, 0);
    tg(hb, f2T, out, nullptr, 32, DMODEL, DFF, DFF, DFF, DMODEL, 128,
       1, 0,0,0,0,0,0,1, ff_b2, nullptr, x1, a_ff, nullptr, 1.f, 0, 0);
}

// round 7
// speedup vs baseline: 7.9807x; 1.0323x over previous
#include <cuda_runtime.h>
#include <cuda_bf16.h>
#include <cstdint>
#include <math.h>

#define MROWS 4096
#define DMODEL 1024
#define VOCAB 32000
#define DFF 2048
#define MD ((size_t)MROWS * DMODEL)

// ---------------- scratch (allocation-free rule) ----------------
__device__ float g_P[(size_t)MROWS * VOCAB];
__device__ float g_tmp[MD], g_x1[MD], g_x2[MD];
__device__ float g_rs[65536];
__device__ __nv_bfloat16 g_Pb[(size_t)MROWS * VOCAB];
__device__ __nv_bfloat16 g_eb[(size_t)VOCAB * DMODEL];
__device__ __nv_bfloat16 g_ebT[(size_t)VOCAB * DMODEL];
__device__ __nv_bfloat16 g_tgtb[MD], g_srcb[MD], g_avb[MD], g_x1b[MD], g_x2b[MD];
__device__ __nv_bfloat16 g_qb[MD], g_kb[MD], g_vtb[MD], g_yb[MD];
__device__ __nv_bfloat16 g_hb[(size_t)MROWS * DFF];
__device__ __nv_bfloat16 g_vawT[(size_t)2 * DMODEL * DMODEL];
__device__ __nv_bfloat16 g_wT[8][(size_t)DMODEL * DMODEL];
__device__ __nv_bfloat16 g_f1T[(size_t)DFF * DMODEL];
__device__ __nv_bfloat16 g_f2T[(size_t)DFF * DMODEL];

// ---------------- PTX helpers ----------------
__device__ __forceinline__ uint32_t smem_u32(const void* p) {
    uint32_t a;
    asm("{ .reg .u64 t; cvta.to.shared.u64 t, %1; cvt.u32.u64 %0, t; }" : "=r"(a) : "l"(p));
    return a;
}
#define CP_ASYNC16(dst, src) \
    asm volatile("cp.async.cg.shared.global [%0], [%1], 16;" \
                 :: "r"(dst), "l"(__cvta_generic_to_global(src)) : "memory")
#define CP_COMMIT() asm volatile("cp.async.commit_group;" ::: "memory")
#define LDSM4(r0, r1, r2, r3, a) \
    asm volatile("ldmatrix.sync.aligned.m8n8.x4.shared.b16 {%0,%1,%2,%3}, [%4];" \
                 : "=r"(r0), "=r"(r1), "=r"(r2), "=r"(r3) : "r"(a))
#define MMA16816(c, a, b) \
    asm volatile("mma.sync.aligned.m16n8k16.row.col.f32.bf16.bf16.f32 " \
                 "{%0,%1,%2,%3}, {%4,%5,%6,%7}, {%8,%9}, {%0,%1,%2,%3};" \
                 : "+f"((c)[0]), "+f"((c)[1]), "+f"((c)[2]), "+f"((c)[3]) \
                 : "r"((a)[0]), "r"((a)[1]), "r"((a)[2]), "r"((a)[3]), \
                   "r"((b)[0]), "r"((b)[1]))

// ---------------- bf16 tensor-core GEMM: C[m][n] = epi(sum_k A[m][k]*B[n][k]) --
// A [.,K] row-major bf16 (lda), B [.,K] row-major bf16 (ldb). Block 128 x NT,
// K-chunk 32, 8 warps (4M x 2N). 4-stage cp.async pipeline, one sync per chunk.
struct GP {
    const __nv_bfloat16 *A, *B;
    float* Cf; __nv_bfloat16* Cb;
    int K, lda, ldb, ldc, Mrows, zInner, act, perm;
    long sAo, sAi, sBo, sBi, sCo, sCi;
    const float *bias, *add, *res, *alpha, *rowScale;
    float scale;
};

template <int NT>
__global__ void __launch_bounds__(256) tgemm_k(GP g)
{
    constexpr int NSUB = NT / 16;
    constexpr int STG = 4;
    constexpr int SMA = 8192;           // 128 rows x 64B
    constexpr int SMB = NT * 64;
    extern __shared__ __align__(128) uint8_t dyn[];
    const uint32_t smA_u = smem_u32(dyn);
    const uint32_t smB_u = smA_u + STG * SMA;

    int tid = threadIdx.x, wid = tid >> 5, lid = tid & 31;
    int wm = wid & 3, wn = wid >> 2;
    int z = blockIdx.z, zo = z / g.zInner, zi = z - zo * g.zInner;
    const __nv_bfloat16* Ab = g.A + zo * g.sAo + zi * g.sAi + (long)blockIdx.x * 128 * g.lda;
    const __nv_bfloat16* Bb = g.B + zo * g.sBo + zi * g.sBi + (long)blockIdx.y * NT * g.ldb;
    long cOff = zo * g.sCo + zi * g.sCi;
    int m0 = blockIdx.x * 128, n0 = blockIdx.y * NT;

    float c[2][NSUB][4];
#pragma unroll
    for (int mt = 0; mt < 2; mt++)
#pragma unroll
        for (int s = 0; s < NSUB; s++)
#pragma unroll
            for (int q = 0; q < 4; q++) c[mt][s][q] = 0.f;

    const int nch = g.K >> 5;

    auto issue = [&](int kc) {
        int kb = kc << 5, buf = kc & (STG - 1);
#pragma unroll
        for (int it = 0; it < 2; it++) {
            int s2 = tid + (it << 8);
            int row = s2 >> 2, seg = s2 & 3;
            uint32_t d = smA_u + buf * SMA + (((row << 2) + (seg ^ ((row >> 1) & 3))) << 4);
            CP_ASYNC16(d, Ab + (long)row * g.lda + kb + (seg << 3));
        }
#pragma unroll
        for (int it = 0; it < NT / 64; it++) {
            int s2 = tid + (it << 8);
            int row = s2 >> 2, seg = s2 & 3;
            uint32_t d = smB_u + buf * SMB + (((row << 2) + (seg ^ ((row >> 1) & 3))) << 4);
            CP_ASYNC16(d, Bb + (long)row * g.ldb + kb + (seg << 3));
        }
        CP_COMMIT();
    };

    // prologue: fill up to STG-1 stages
    for (int kc = 0; kc < STG - 1 && kc < nch; kc++) issue(kc);

    int mi = lid >> 3, j = lid & 7;
    for (int kc = 0; kc < nch; kc++) {
        // wait until chunk kc has landed (committed so far = min(nch, kc+STG-1))
        int allowed = nch - 1 - kc;
        if (allowed > STG - 2) allowed = STG - 2;
        if (allowed >= 2)      asm volatile("cp.async.wait_group 2;" ::: "memory");
        else if (allowed == 1) asm volatile("cp.async.wait_group 1;" ::: "memory");
        else                   asm volatile("cp.async.wait_group 0;" ::: "memory");
        __syncthreads();

        if (kc + STG - 1 < nch) issue(kc + STG - 1);

        int buf = kc & (STG - 1);
        uint32_t Abase = smA_u + buf * SMA;
        uint32_t Bbase = smB_u + buf * SMB;
#pragma unroll
        for (int ks = 0; ks < 2; ks++) {
            uint32_t aF[2][4];
#pragma unroll
            for (int mt = 0; mt < 2; mt++) {
                int arow = wm * 32 + mt * 16 + ((mi & 1) << 3) + j;
                int aseg = (ks << 1) + (mi >> 1);
                uint32_t ad = Abase + (((arow << 2) + (aseg ^ ((arow >> 1) & 3))) << 4);
                LDSM4(aF[mt][0], aF[mt][1], aF[mt][2], aF[mt][3], ad);
            }
            uint32_t bF[NSUB][2];
#pragma unroll
            for (int gi = 0; gi < NT / 32; gi++) {
                int nrow = wn * (NT / 2) + gi * 16 + ((mi >> 1) << 3) + j;
                int bseg = (ks << 1) + (mi & 1);
                uint32_t bd = Bbase + (((nrow << 2) + (bseg ^ ((nrow >> 1) & 3))) << 4);
                uint32_t r0, r1, r2, r3;
                LDSM4(r0, r1, r2, r3, bd);
                bF[2 * gi][0] = r0; bF[2 * gi][1] = r1;
                bF[2 * gi + 1][0] = r2; bF[2 * gi + 1][1] = r3;
            }
#pragma unroll
            for (int mt = 0; mt < 2; mt++)
#pragma unroll
                for (int s = 0; s < NSUB; s++)
                    MMA16816(c[mt][s], aF[mt], bF[s]);
        }
    }

    // ---- epilogue ----
    float alpha = g.alpha ? *g.alpha : 1.0f;
#pragma unroll
    for (int mt = 0; mt < 2; mt++) {
#pragma unroll
        for (int s = 0; s < NSUB; s++) {
            int rA = m0 + wm * 32 + mt * 16 + (lid >> 2);
            int nn = n0 + wn * (NT / 2) + s * 8 + ((lid & 3) << 1);
#pragma unroll
            for (int hh = 0; hh < 2; hh++) {
                int r = rA + hh * 8;
                float sc = g.scale * (g.rowScale ? g.rowScale[(long)z * g.Mrows + r] : 1.f);
                long rowbase = cOff + (long)r * g.ldc;
#pragma unroll
                for (int w = 0; w < 2; w++) {
                    int n = nn + w;
                    float v = c[mt][s][hh * 2 + w] * sc;
                    if (g.bias) v += __ldg(g.bias + n);
                    long idx = rowbase + n;
                    if (g.add) v += g.add[idx];
                    if (g.act == 1) v = fmaxf(v, 0.f);
                    else if (g.act == 2) v = v > 0.f ? v : 0.01f * v;
                    if (g.res) v = g.res[idx] + alpha * v;
                    if (g.Cf) g.Cf[idx] = v;
                    if (g.Cb) {
                        long bi;
                        if (g.perm == 0) bi = idx;
                        else {
                            int bb = r >> 10, l = r & 1023, h = n >> 6, dd = n & 63;
                            long bh = (bb << 4) + h;
                            bi = (g.perm == 1) ? ((bh << 10) + l) * 64 + dd
                                               : ((bh << 6) + dd) * 1024 + l;
                        }
                        g.Cb[bi] = __float2bfloat16(v);
                    }
                }
            }
        }
    }
}

// ---------------- softmax: fp32 in -> unnormalized bf16 exp + 1/rowsum -------
__device__ __forceinline__ float fexp(float x) {
    float t = fmaxf(x * 1.4426950408889634f, -126.0f);
    int i = __float2int_rd(t);
    float f = t - (float)i;
    float p = 1.f + f * (0.69314718f + f * (0.24022651f + f * (0.05550411f +
              f * (0.00961812f + f * 0.00133336f))));
    return __int_as_float((i + 127) << 23) * p;
}

__global__ void __launch_bounds__(256) softmax_bf_k(
    const float* __restrict__ in, __nv_bfloat16* __restrict__ out,
    float* __restrict__ invsum, int ncols)
{
    long row = blockIdx.x;
    const float4* p = (const float4*)(in + row * (long)ncols);
    uint2* o = (uint2*)(out + row * (long)ncols);
    int nq = ncols >> 2, tid = threadIdx.x;
    __shared__ float red[256];

    float m = -1e30f;
    for (int i = tid; i < nq; i += 256) {
        float4 v = p[i];
        m = fmaxf(m, fmaxf(fmaxf(v.x, v.y), fmaxf(v.z, v.w)));
    }
    red[tid] = m; __syncthreads();
    for (int o2 = 128; o2; o2 >>= 1) {
        if (tid < o2) red[tid] = fmaxf(red[tid], red[tid + o2]);
        __syncthreads();
    }
    m = red[0]; __syncthreads();

    float s = 0.f;
    for (int i = tid; i < nq; i += 256) {
        float4 v = p[i];
        float e0 = fexp(v.x - m), e1 = fexp(v.y - m);
        float e2 = fexp(v.z - m), e3 = fexp(v.w - m);
        s += (e0 + e1) + (e2 + e3);
        __nv_bfloat162 lo = __floats2bfloat162_rn(e0, e1);
        __nv_bfloat162 hi = __floats2bfloat162_rn(e2, e3);
        uint2 u; u.x = *(uint32_t*)&lo; u.y = *(uint32_t*)&hi;
        o[i] = u;
    }
    red[tid] = s; __syncthreads();
    for (int o2 = 128; o2; o2 >>= 1) {
        if (tid < o2) red[tid] += red[tid + o2];
        __syncthreads();
    }
    if (tid == 0) invsum[row] = 1.0f / red[0];
}

// ---------------- conversions ----------------
__global__ void __launch_bounds__(256) conv_k(const float* __restrict__ s,
                                              __nv_bfloat16* __restrict__ d, long n)
{
    long i = ((long)blockIdx.x * 256 + threadIdx.x) << 2;
    if (i < n) {
        float4 v = *(const float4*)(s + i);
        __nv_bfloat162 lo = __floats2bfloat162_rn(v.x, v.y);
        __nv_bfloat162 hi = __floats2bfloat162_rn(v.z, v.w);
        uint2 u; u.x = *(uint32_t*)&lo; u.y = *(uint32_t*)&hi;
        *(uint2*)(d + i) = u;
    }
}
__global__ void convT_k(const float* __restrict__ s, __nv_bfloat16* __restrict__ d,
                        int R, int C)
{
    __shared__ float t[32][33];
    int c0 = blockIdx.x << 5, r0 = blockIdx.y << 5;
    int x = threadIdx.x, y = threadIdx.y;
#pragma unroll
    for (int i = 0; i < 32; i += 8)
        t[y + i][x] = s[(long)(r0 + y + i) * C + c0 + x];
    __syncthreads();
#pragma unroll
    for (int i = 0; i < 32; i += 8)
        d[(long)(c0 + y + i) * R + r0 + x] = __float2bfloat16(t[x][y + i]);
}

// ---------------- host helpers ----------------
static void conv(const float* s, __nv_bfloat16* d, long n) {
    conv_k<<<(unsigned)((n / 4 + 255) / 256), 256>>>(s, d, n);
}
static void convT(const float* s, __nv_bfloat16* d, int R, int C) {
    convT_k<<<dim3(C / 32, R / 32), dim3(32, 8)>>>(s, d, R, C);
}

static void tg(const __nv_bfloat16* A, const __nv_bfloat16* B, float* Cf, __nv_bfloat16* Cb,
               int Mtiles, int Ntot, int K, int lda, int ldb, int ldc, int NT,
               int batch = 1,
               long sAo = 0, long sAi = 0, long sBo = 0, long sBi = 0,
               long sCo = 0, long sCi = 0, int zInner = 1,
               const float* bias = nullptr, const float* add = nullptr,
               const float* res = nullptr, const float* alpha = nullptr,
               const float* rowScale = nullptr, float scale = 1.0f,
               int act = 0, int perm = 0)
{
    GP g;
    g.A = A; g.B = B; g.Cf = Cf; g.Cb = Cb;
    g.K = K; g.lda = lda; g.ldb = ldb; g.ldc = ldc;
    g.Mrows = Mtiles * 128; g.zInner = zInner; g.act = act; g.perm = perm;
    g.sAo = sAo; g.sAi = sAi; g.sBo = sBo; g.sBi = sBi; g.sCo = sCo; g.sCi = sCi;
    g.bias = bias; g.add = add; g.res = res; g.alpha = alpha; g.rowScale = rowScale;
    g.scale = scale;
    dim3 grid(Mtiles, Ntot / NT, batch);
    if (NT == 128) {
        static bool done = false;
        if (!done) {
            cudaFuncSetAttribute(tgemm_k<128>,
                                 cudaFuncAttributeMaxDynamicSharedMemorySize, 65536);
            done = true;
        }
        tgemm_k<128><<<grid, 256, 65536>>>(g);
    } else {
        static bool done = false;
        if (!done) {
            cudaFuncSetAttribute(tgemm_k<64>,
                                 cudaFuncAttributeMaxDynamicSharedMemorySize, 49152);
            done = true;
        }
        tgemm_k<64><<<grid, 256, 49152>>>(g);
    }
}

extern "C" void kernel_launch(void* const* d_in, const int* in_sizes, int n_in,
                              void* d_out, int out_size)
{
    const float* tgt   = (const float*)d_in[0];
    const float* src   = (const float*)d_in[1];
    const float* emb   = (const float*)d_in[2];
    const float* va_w  = (const float*)d_in[3];
    const float* va_b  = (const float*)d_in[4];
    const float* a_va  = (const float*)d_in[5];
    const float* sa_wq = (const float*)d_in[6];
    const float* sa_bq = (const float*)d_in[7];
    const float* sa_wk = (const float*)d_in[8];
    const float* sa_bk = (const float*)d_in[9];
    const float* sa_wv = (const float*)d_in[10];
    const float* sa_bv = (const float*)d_in[11];
    const float* sa_wo = (const float*)d_in[12];
    const float* sa_bo = (const float*)d_in[13];
    const float* a_sa  = (const float*)d_in[14];
    const float* ca_wq = (const float*)d_in[15];
    const float* ca_bq = (const float*)d_in[16];
    const float* ca_wk = (const float*)d_in[17];
    const float* ca_bk = (const float*)d_in[18];
    const float* ca_wv = (const float*)d_in[19];
    const float* ca_bv = (const float*)d_in[20];
    const float* ca_wo = (const float*)d_in[21];
    const float* ca_bo = (const float*)d_in[22];
    const float* a_ca  = (const float*)d_in[23];
    const float* ff_w1 = (const float*)d_in[24];
    const float* ff_b1 = (const float*)d_in[25];
    const float* ff_w2 = (const float*)d_in[26];
    const float* ff_b2 = (const float*)d_in[27];
    const float* a_ff  = (const float*)d_in[28];
    float* out = (float*)d_out;

    void* p;
    cudaGetSymbolAddress(&p, g_P);    float* P    = (float*)p;
    cudaGetSymbolAddress(&p, g_tmp);  float* tmp  = (float*)p;
    cudaGetSymbolAddress(&p, g_x1);   float* x1   = (float*)p;
    cudaGetSymbolAddress(&p, g_x2);   float* x2   = (float*)p;
    cudaGetSymbolAddress(&p, g_rs);   float* rs   = (float*)p;
    cudaGetSymbolAddress(&p, g_Pb);   __nv_bfloat16* Pb   = (__nv_bfloat16*)p;
    cudaGetSymbolAddress(&p, g_eb);   __nv_bfloat16* eb   = (__nv_bfloat16*)p;
    cudaGetSymbolAddress(&p, g_ebT);  __nv_bfloat16* ebT  = (__nv_bfloat16*)p;
    cudaGetSymbolAddress(&p, g_tgtb); __nv_bfloat16* tgtb = (__nv_bfloat16*)p;
    cudaGetSymbolAddress(&p, g_srcb); __nv_bfloat16* srcb = (__nv_bfloat16*)p;
    cudaGetSymbolAddress(&p, g_avb);  __nv_bfloat16* avb  = (__nv_bfloat16*)p;
    cudaGetSymbolAddress(&p, g_x1b);  __nv_bfloat16* x1b  = (__nv_bfloat16*)p;
    cudaGetSymbolAddress(&p, g_x2b);  __nv_bfloat16* x2b  = (__nv_bfloat16*)p;
    cudaGetSymbolAddress(&p, g_qb);   __nv_bfloat16* qb   = (__nv_bfloat16*)p;
    cudaGetSymbolAddress(&p, g_kb);   __nv_bfloat16* kb   = (__nv_bfloat16*)p;
    cudaGetSymbolAddress(&p, g_vtb);  __nv_bfloat16* vtb  = (__nv_bfloat16*)p;
    cudaGetSymbolAddress(&p, g_yb);   __nv_bfloat16* yb   = (__nv_bfloat16*)p;
    cudaGetSymbolAddress(&p, g_hb);   __nv_bfloat16* hb   = (__nv_bfloat16*)p;
    cudaGetSymbolAddress(&p, g_vawT); __nv_bfloat16* vawT = (__nv_bfloat16*)p;
    cudaGetSymbolAddress(&p, g_wT);   __nv_bfloat16* wT   = (__nv_bfloat16*)p;
    cudaGetSymbolAddress(&p, g_f1T);  __nv_bfloat16* f1T  = (__nv_bfloat16*)p;
    cudaGetSymbolAddress(&p, g_f2T);  __nv_bfloat16* f2T  = (__nv_bfloat16*)p;
    const size_t WSZ = (size_t)DMODEL * DMODEL;

    conv(emb, eb, (long)VOCAB * DMODEL);
    convT(emb, ebT, VOCAB, DMODEL);
    conv(tgt, tgtb, (long)MD);
    conv(src, srcb, (long)MD);
    convT(va_w,  vawT,         2 * DMODEL, DMODEL);
    convT(sa_wq, wT + 0 * WSZ, DMODEL, DMODEL);
    convT(sa_wk, wT + 1 * WSZ, DMODEL, DMODEL);
    convT(sa_wv, wT + 2 * WSZ, DMODEL, DMODEL);
    convT(sa_wo, wT + 3 * WSZ, DMODEL, DMODEL);
    convT(ca_wq, wT + 4 * WSZ, DMODEL, DMODEL);
    convT(ca_wk, wT + 5 * WSZ, DMODEL, DMODEL);
    convT(ca_wv, wT + 6 * WSZ, DMODEL, DMODEL);
    convT(ca_wo, wT + 7 * WSZ, DMODEL, DMODEL);
    convT(ff_w1, f1T, DMODEL, DFF);
    convT(ff_w2, f2T, DFF, DMODEL);

    const float inv_sd = 1.0f / 32.0f;
    const long sQ = 65536, sS = 1048576;

    // ===== Vocabulary attention =====
    tg(tgtb, eb, P, nullptr, 32, VOCAB, DMODEL, DMODEL, DMODEL, VOCAB, 128);
    softmax_bf_k<<<MROWS, 256>>>(P, Pb, rs, VOCAB);
    tg(Pb, ebT, nullptr, avb, 32, DMODEL, VOCAB, VOCAB, VOCAB, DMODEL, 128,
       1, 0,0,0,0,0,0,1, nullptr, nullptr, nullptr, nullptr, rs);
    tg(avb, vawT + DMODEL, tmp, nullptr, 32, DMODEL, DMODEL, DMODEL, 2 * DMODEL, DMODEL, 128);
    tg(tgtb, vawT, x1, x1b, 32, DMODEL, DMODEL, DMODEL, 2 * DMODEL, DMODEL, 128,
       1, 0,0,0,0,0,0,1, va_b, tmp, tgt, a_va);

    // ===== Self attention =====
    tg(x1b, wT + 0 * WSZ, nullptr, qb, 32, DMODEL, DMODEL, DMODEL, DMODEL, DMODEL, 128,
       1, 0,0,0,0,0,0,1, sa_bq, nullptr, nullptr, nullptr, nullptr, 1.f, 1, 1);
    tg(x1b, wT + 1 * WSZ, nullptr, kb, 32, DMODEL, DMODEL, DMODEL, DMODEL, DMODEL, 128,
       1, 0,0,0,0,0,0,1, sa_bk, nullptr, nullptr, nullptr, nullptr, 1.f, 1, 1);
    tg(x1b, wT + 2 * WSZ, nullptr, vtb, 32, DMODEL, DMODEL, DMODEL, DMODEL, DMODEL, 128,
       1, 0,0,0,0,0,0,1, sa_bv, nullptr, nullptr, nullptr, nullptr, 1.f, 1, 2);
    tg(qb, kb, P, nullptr, 8, 1024, 64, 64, 64, 1024, 128,
       64, sQ, 0, sQ, 0, sS, 0, 1,
       nullptr, nullptr, nullptr, nullptr, nullptr, inv_sd);
    softmax_bf_k<<<65536, 256>>>(P, Pb, rs, 1024);
    tg(Pb, vtb, nullptr, yb, 8, 64, 1024, 1024, 1024, DMODEL, 64,
       64, 16L * sS, sS, 16L * sQ, sQ, (long)1024 * DMODEL, 64, 16,
       nullptr, nullptr, nullptr, nullptr, rs);
    tg(yb, wT + 3 * WSZ, x2, x2b, 32, DMODEL, DMODEL, DMODEL, DMODEL, DMODEL, 128,
       1, 0,0,0,0,0,0,1, sa_bo, nullptr, x1, a_sa, nullptr, 1.f, 1, 0);

    // ===== Cross attention =====
    tg(x2b, wT + 4 * WSZ, nullptr, qb, 32, DMODEL, DMODEL, DMODEL, DMODEL, DMODEL, 128,
       1, 0,0,0,0,0,0,1, ca_bq, nullptr, nullptr, nullptr, nullptr, 1.f, 1, 1);
    tg(srcb, wT + 5 * WSZ, nullptr, kb, 32, DMODEL, DMODEL, DMODEL, DMODEL, DMODEL, 128,
       1, 0,0,0,0,0,0,1, ca_bk, nullptr, nullptr, nullptr, nullptr, 1.f, 1, 1);
    tg(srcb, wT + 6 * WSZ, nullptr, vtb, 32, DMODEL, DMODEL, DMODEL, DMODEL, DMODEL, 128,
       1, 0,0,0,0,0,0,1, ca_bv, nullptr, nullptr, nullptr, nullptr, 1.f, 1, 2);
    tg(qb, kb, P, nullptr, 8, 1024, 64, 64, 64, 1024, 128,
       64, sQ, 0, sQ, 0, sS, 0, 1,
       nullptr, nullptr, nullptr, nullptr, nullptr, inv_sd);
    softmax_bf_k<<<65536, 256>>>(P, Pb, rs, 1024);
    tg(Pb, vtb, nullptr, yb, 8, 64, 1024, 1024, 1024, DMODEL, 64,
       64, 16L * sS, sS, 16L * sQ, sQ, (long)1024 * DMODEL, 64, 16,
       nullptr, nullptr, nullptr, nullptr, rs);
    tg(yb, wT + 7 * WSZ, x1, x1b, 32, DMODEL, DMODEL, DMODEL, DMODEL, DMODEL, 128,
       1, 0,0,0,0,0,0,1, ca_bo, nullptr, x2, a_ca, nullptr, 1.f, 1, 0);

    // ===== Feed forward =====
    tg(x1b, f1T, nullptr, hb, 32, DFF, DMODEL, DMODEL, DMODEL, DFF, 128,
       1, 0,0,0,0,0,0,1, ff_b1, nullptr, nullptr, nullptr, nullptr, 1.f, 2, 0);
    tg(hb, f2T, out, nullptr, 32, DMODEL, DFF, DFF, DFF, DMODEL, 128,
       1, 0,0,0,0,0,0,1, ff_b2, nullptr, x1, a_ff, nullptr, 1.f, 0, 0);
}

// round 8
// speedup vs baseline: 8.3595x; 1.0475x over previous
#include <cuda_runtime.h>
#include <cuda_bf16.h>
#include <cstdint>
#include <math.h>

#define MROWS 4096
#define DMODEL 1024
#define VOCAB 32000
#define DFF 2048
#define MD ((size_t)MROWS * DMODEL)

// ---------------- scratch (allocation-free rule) ----------------
__device__ float g_tmp[MD], g_x1[MD], g_x2[MD];
__device__ float g_rs[65536];
__device__ __nv_bfloat16 g_Pb[(size_t)MROWS * VOCAB];
__device__ __nv_bfloat16 g_eb[(size_t)VOCAB * DMODEL];
__device__ __nv_bfloat16 g_ebT[(size_t)VOCAB * DMODEL];
__device__ __nv_bfloat16 g_tgtb[MD], g_srcb[MD], g_avb[MD], g_x1b[MD], g_x2b[MD];
__device__ __nv_bfloat16 g_qb[MD], g_kb[MD], g_vtb[MD], g_yb[MD];
__device__ __nv_bfloat16 g_hb[(size_t)MROWS * DFF];
__device__ __nv_bfloat16 g_vawT[(size_t)2 * DMODEL * DMODEL];
__device__ __nv_bfloat16 g_wT[8][(size_t)DMODEL * DMODEL];
__device__ __nv_bfloat16 g_f1T[(size_t)DFF * DMODEL];
__device__ __nv_bfloat16 g_f2T[(size_t)DFF * DMODEL];

// ---------------- PTX helpers ----------------
__device__ __forceinline__ uint32_t smem_u32(const void* p) {
    uint32_t a;
    asm("{ .reg .u64 t; cvta.to.shared.u64 t, %1; cvt.u32.u64 %0, t; }" : "=r"(a) : "l"(p));
    return a;
}
#define CP_ASYNC16(dst, src) \
    asm volatile("cp.async.cg.shared.global [%0], [%1], 16;" \
                 :: "r"(dst), "l"(__cvta_generic_to_global(src)) : "memory")
#define CP_COMMIT() asm volatile("cp.async.commit_group;" ::: "memory")
#define LDSM4(r0, r1, r2, r3, a) \
    asm volatile("ldmatrix.sync.aligned.m8n8.x4.shared.b16 {%0,%1,%2,%3}, [%4];" \
                 : "=r"(r0), "=r"(r1), "=r"(r2), "=r"(r3) : "r"(a))
#define MMA16816(c, a, b) \
    asm volatile("mma.sync.aligned.m16n8k16.row.col.f32.bf16.bf16.f32 " \
                 "{%0,%1,%2,%3}, {%4,%5,%6,%7}, {%8,%9}, {%0,%1,%2,%3};" \
                 : "+f"((c)[0]), "+f"((c)[1]), "+f"((c)[2]), "+f"((c)[3]) \
                 : "r"((a)[0]), "r"((a)[1]), "r"((a)[2]), "r"((a)[3]), \
                   "r"((b)[0]), "r"((b)[1]))

// fp32 exp via FMA-pipe exp2 poly (no MUFU bottleneck)
__device__ __forceinline__ float fexp(float x) {
    float t = fmaxf(x * 1.4426950408889634f, -126.0f);
    int i = __float2int_rd(t);
    float f = t - (float)i;
    float p = 1.f + f * (0.69314718f + f * (0.24022651f + f * (0.05550411f +
              f * (0.00961812f + f * 0.00133336f))));
    return __int_as_float((i + 127) << 23) * p;
}

// ---------------- bf16 tensor-core GEMM: C[m][n] = epi(sum_k A[m][k]*B[n][k]) --
// Block 128 x NT, K-chunk 32, 8 warps (4M x 2N), 4-stage cp.async pipeline.
// Epilogue: v = acc*scale*rowScale[m]; +bias; +add; act (1=relu,2=leaky,3=exp);
//           rsum: atomic per-row sum of post-act values; res + alpha*v;
//           write Cf (fp32) and/or Cb (bf16, optional head-permute).
struct GP {
    const __nv_bfloat16 *A, *B;
    float* Cf; __nv_bfloat16* Cb;
    int K, lda, ldb, ldc, Mrows, zInner, act, perm;
    long sAo, sAi, sBo, sBi, sCo, sCi;
    const float *bias, *add, *res, *alpha, *rowScale;
    float* rsum;
    float scale;
};

template <int NT>
__global__ void __launch_bounds__(256) tgemm_k(GP g)
{
    constexpr int NSUB = NT / 16;
    constexpr int STG = 4;
    constexpr int SMA = 8192;
    constexpr int SMB = NT * 64;
    extern __shared__ __align__(128) uint8_t dyn[];
    const uint32_t smA_u = smem_u32(dyn);
    const uint32_t smB_u = smA_u + STG * SMA;

    int tid = threadIdx.x, wid = tid >> 5, lid = tid & 31;
    int wm = wid & 3, wn = wid >> 2;
    int z = blockIdx.z, zo = z / g.zInner, zi = z - zo * g.zInner;
    const __nv_bfloat16* Ab = g.A + zo * g.sAo + zi * g.sAi + (long)blockIdx.x * 128 * g.lda;
    const __nv_bfloat16* Bb = g.B + zo * g.sBo + zi * g.sBi + (long)blockIdx.y * NT * g.ldb;
    long cOff = zo * g.sCo + zi * g.sCi;
    int m0 = blockIdx.x * 128, n0 = blockIdx.y * NT;

    float c[2][NSUB][4];
#pragma unroll
    for (int mt = 0; mt < 2; mt++)
#pragma unroll
        for (int s = 0; s < NSUB; s++)
#pragma unroll
            for (int q = 0; q < 4; q++) c[mt][s][q] = 0.f;

    const int nch = g.K >> 5;

    auto issue = [&](int kc) {
        int kb = kc << 5, buf = kc & (STG - 1);
#pragma unroll
        for (int it = 0; it < 2; it++) {
            int s2 = tid + (it << 8);
            int row = s2 >> 2, seg = s2 & 3;
            uint32_t d = smA_u + buf * SMA + (((row << 2) + (seg ^ ((row >> 1) & 3))) << 4);
            CP_ASYNC16(d, Ab + (long)row * g.lda + kb + (seg << 3));
        }
#pragma unroll
        for (int it = 0; it < NT / 64; it++) {
            int s2 = tid + (it << 8);
            int row = s2 >> 2, seg = s2 & 3;
            uint32_t d = smB_u + buf * SMB + (((row << 2) + (seg ^ ((row >> 1) & 3))) << 4);
            CP_ASYNC16(d, Bb + (long)row * g.ldb + kb + (seg << 3));
        }
        CP_COMMIT();
    };

    for (int kc = 0; kc < STG - 1 && kc < nch; kc++) issue(kc);

    int mi = lid >> 3, j = lid & 7;
    for (int kc = 0; kc < nch; kc++) {
        int allowed = nch - 1 - kc;
        if (allowed > STG - 2) allowed = STG - 2;
        if (allowed >= 2)      asm volatile("cp.async.wait_group 2;" ::: "memory");
        else if (allowed == 1) asm volatile("cp.async.wait_group 1;" ::: "memory");
        else                   asm volatile("cp.async.wait_group 0;" ::: "memory");
        __syncthreads();

        if (kc + STG - 1 < nch) issue(kc + STG - 1);

        int buf = kc & (STG - 1);
        uint32_t Abase = smA_u + buf * SMA;
        uint32_t Bbase = smB_u + buf * SMB;
#pragma unroll
        for (int ks = 0; ks < 2; ks++) {
            uint32_t aF[2][4];
#pragma unroll
            for (int mt = 0; mt < 2; mt++) {
                int arow = wm * 32 + mt * 16 + ((mi & 1) << 3) + j;
                int aseg = (ks << 1) + (mi >> 1);
                uint32_t ad = Abase + (((arow << 2) + (aseg ^ ((arow >> 1) & 3))) << 4);
                LDSM4(aF[mt][0], aF[mt][1], aF[mt][2], aF[mt][3], ad);
            }
            uint32_t bF[NSUB][2];
#pragma unroll
            for (int gi = 0; gi < NT / 32; gi++) {
                int nrow = wn * (NT / 2) + gi * 16 + ((mi >> 1) << 3) + j;
                int bseg = (ks << 1) + (mi & 1);
                uint32_t bd = Bbase + (((nrow << 2) + (bseg ^ ((nrow >> 1) & 3))) << 4);
                uint32_t r0, r1, r2, r3;
                LDSM4(r0, r1, r2, r3, bd);
                bF[2 * gi][0] = r0; bF[2 * gi][1] = r1;
                bF[2 * gi + 1][0] = r2; bF[2 * gi + 1][1] = r3;
            }
#pragma unroll
            for (int mt = 0; mt < 2; mt++)
#pragma unroll
                for (int s = 0; s < NSUB; s++)
                    MMA16816(c[mt][s], aF[mt], bF[s]);
        }
    }

    // ---- epilogue ----
    float alpha = g.alpha ? *g.alpha : 1.0f;
#pragma unroll
    for (int mt = 0; mt < 2; mt++) {
        float lsum[2] = {0.f, 0.f};
#pragma unroll
        for (int s = 0; s < NSUB; s++) {
            int rA = m0 + wm * 32 + mt * 16 + (lid >> 2);
            int nn = n0 + wn * (NT / 2) + s * 8 + ((lid & 3) << 1);
#pragma unroll
            for (int hh = 0; hh < 2; hh++) {
                int r = rA + hh * 8;
                float sc = g.scale * (g.rowScale ? g.rowScale[(long)z * g.Mrows + r] : 1.f);
                long rowbase = cOff + (long)r * g.ldc;
#pragma unroll
                for (int w = 0; w < 2; w++) {
                    int n = nn + w;
                    float v = c[mt][s][hh * 2 + w] * sc;
                    if (g.bias) v += __ldg(g.bias + n);
                    long idx = rowbase + n;
                    if (g.add) v += g.add[idx];
                    if (g.act == 1) v = fmaxf(v, 0.f);
                    else if (g.act == 2) v = v > 0.f ? v : 0.01f * v;
                    else if (g.act == 3) v = fexp(v);
                    if (g.rsum) lsum[hh] += v;
                    if (g.res) v = g.res[idx] + alpha * v;
                    if (g.Cf) g.Cf[idx] = v;
                    if (g.Cb) {
                        long bi;
                        if (g.perm == 0) bi = idx;
                        else {
                            int bb = r >> 10, l = r & 1023, h = n >> 6, dd = n & 63;
                            long bh = (bb << 4) + h;
                            bi = (g.perm == 1) ? ((bh << 10) + l) * 64 + dd
                                               : ((bh << 6) + dd) * 1024 + l;
                        }
                        g.Cb[bi] = __float2bfloat16(v);
                    }
                }
            }
        }
        if (g.rsum) {
            int rA = m0 + wm * 32 + mt * 16 + (lid >> 2);
#pragma unroll
            for (int hh = 0; hh < 2; hh++) {
                float t = lsum[hh];
                t += __shfl_xor_sync(0xffffffffu, t, 1);
                t += __shfl_xor_sync(0xffffffffu, t, 2);
                if ((lid & 3) == 0)
                    atomicAdd(g.rsum + (long)z * g.Mrows + rA + hh * 8, t);
            }
        }
    }
}

// ---------------- small utility kernels ----------------
__global__ void zero_k(float* __restrict__ p, int n) {
    int i = blockIdx.x * 256 + threadIdx.x;
    if (i < n) p[i] = 0.f;
}
__global__ void recip_k(float* __restrict__ p, int n) {
    int i = blockIdx.x * 256 + threadIdx.x;
    if (i < n) p[i] = 1.0f / p[i];
}

// ---------------- conversions ----------------
__global__ void __launch_bounds__(256) conv_k(const float* __restrict__ s,
                                              __nv_bfloat16* __restrict__ d, long n)
{
    long i = ((long)blockIdx.x * 256 + threadIdx.x) << 2;
    if (i < n) {
        float4 v = *(const float4*)(s + i);
        __nv_bfloat162 lo = __floats2bfloat162_rn(v.x, v.y);
        __nv_bfloat162 hi = __floats2bfloat162_rn(v.z, v.w);
        uint2 u; u.x = *(uint32_t*)&lo; u.y = *(uint32_t*)&hi;
        *(uint2*)(d + i) = u;
    }
}
__global__ void convT_k(const float* __restrict__ s, __nv_bfloat16* __restrict__ d,
                        int R, int C)
{
    __shared__ float t[32][33];
    int c0 = blockIdx.x << 5, r0 = blockIdx.y << 5;
    int x = threadIdx.x, y = threadIdx.y;
#pragma unroll
    for (int i = 0; i < 32; i += 8)
        t[y + i][x] = s[(long)(r0 + y + i) * C + c0 + x];
    __syncthreads();
#pragma unroll
    for (int i = 0; i < 32; i += 8)
        d[(long)(c0 + y + i) * R + r0 + x] = __float2bfloat16(t[x][y + i]);
}

// ---------------- host helpers ----------------
static void conv(const float* s, __nv_bfloat16* d, long n) {
    conv_k<<<(unsigned)((n / 4 + 255) / 256), 256>>>(s, d, n);
}
static void convT(const float* s, __nv_bfloat16* d, int R, int C) {
    convT_k<<<dim3(C / 32, R / 32), dim3(32, 8)>>>(s, d, R, C);
}

static void tg(const __nv_bfloat16* A, const __nv_bfloat16* B, float* Cf, __nv_bfloat16* Cb,
               int Mtiles, int Ntot, int K, int lda, int ldb, int ldc, int NT,
               int batch = 1,
               long sAo = 0, long sAi = 0, long sBo = 0, long sBi = 0,
               long sCo = 0, long sCi = 0, int zInner = 1,
               const float* bias = nullptr, const float* add = nullptr,
               const float* res = nullptr, const float* alpha = nullptr,
               const float* rowScale = nullptr, float scale = 1.0f,
               int act = 0, int perm = 0, float* rsum = nullptr)
{
    GP g;
    g.A = A; g.B = B; g.Cf = Cf; g.Cb = Cb;
    g.K = K; g.lda = lda; g.ldb = ldb; g.ldc = ldc;
    g.Mrows = Mtiles * 128; g.zInner = zInner; g.act = act; g.perm = perm;
    g.sAo = sAo; g.sAi = sAi; g.sBo = sBo; g.sBi = sBi; g.sCo = sCo; g.sCi = sCi;
    g.bias = bias; g.add = add; g.res = res; g.alpha = alpha; g.rowScale = rowScale;
    g.rsum = rsum; g.scale = scale;
    dim3 grid(Mtiles, Ntot / NT, batch);
    if (NT == 128) {
        static bool done = false;
        if (!done) {
            cudaFuncSetAttribute(tgemm_k<128>,
                                 cudaFuncAttributeMaxDynamicSharedMemorySize, 65536);
            done = true;
        }
        tgemm_k<128><<<grid, 256, 65536>>>(g);
    } else {
        static bool done = false;
        if (!done) {
            cudaFuncSetAttribute(tgemm_k<64>,
                                 cudaFuncAttributeMaxDynamicSharedMemorySize, 49152);
            done = true;
        }
        tgemm_k<64><<<grid, 256, 49152>>>(g);
    }
}

extern "C" void kernel_launch(void* const* d_in, const int* in_sizes, int n_in,
                              void* d_out, int out_size)
{
    const float* tgt   = (const float*)d_in[0];
    const float* src   = (const float*)d_in[1];
    const float* emb   = (const float*)d_in[2];
    const float* va_w  = (const float*)d_in[3];
    const float* va_b  = (const float*)d_in[4];
    const float* a_va  = (const float*)d_in[5];
    const float* sa_wq = (const float*)d_in[6];
    const float* sa_bq = (const float*)d_in[7];
    const float* sa_wk = (const float*)d_in[8];
    const float* sa_bk = (const float*)d_in[9];
    const float* sa_wv = (const float*)d_in[10];
    const float* sa_bv = (const float*)d_in[11];
    const float* sa_wo = (const float*)d_in[12];
    const float* sa_bo = (const float*)d_in[13];
    const float* a_sa  = (const float*)d_in[14];
    const float* ca_wq = (const float*)d_in[15];
    const float* ca_bq = (const float*)d_in[16];
    const float* ca_wk = (const float*)d_in[17];
    const float* ca_bk = (const float*)d_in[18];
    const float* ca_wv = (const float*)d_in[19];
    const float* ca_bv = (const float*)d_in[20];
    const float* ca_wo = (const float*)d_in[21];
    const float* ca_bo = (const float*)d_in[22];
    const float* a_ca  = (const float*)d_in[23];
    const float* ff_w1 = (const float*)d_in[24];
    const float* ff_b1 = (const float*)d_in[25];
    const float* ff_w2 = (const float*)d_in[26];
    const float* ff_b2 = (const float*)d_in[27];
    const float* a_ff  = (const float*)d_in[28];
    float* out = (float*)d_out;

    void* p;
    cudaGetSymbolAddress(&p, g_tmp);  float* tmp  = (float*)p;
    cudaGetSymbolAddress(&p, g_x1);   float* x1   = (float*)p;
    cudaGetSymbolAddress(&p, g_x2);   float* x2   = (float*)p;
    cudaGetSymbolAddress(&p, g_rs);   float* rs   = (float*)p;
    cudaGetSymbolAddress(&p, g_Pb);   __nv_bfloat16* Pb   = (__nv_bfloat16*)p;
    cudaGetSymbolAddress(&p, g_eb);   __nv_bfloat16* eb   = (__nv_bfloat16*)p;
    cudaGetSymbolAddress(&p, g_ebT);  __nv_bfloat16* ebT  = (__nv_bfloat16*)p;
    cudaGetSymbolAddress(&p, g_tgtb); __nv_bfloat16* tgtb = (__nv_bfloat16*)p;
    cudaGetSymbolAddress(&p, g_srcb); __nv_bfloat16* srcb = (__nv_bfloat16*)p;
    cudaGetSymbolAddress(&p, g_avb);  __nv_bfloat16* avb  = (__nv_bfloat16*)p;
    cudaGetSymbolAddress(&p, g_x1b);  __nv_bfloat16* x1b  = (__nv_bfloat16*)p;
    cudaGetSymbolAddress(&p, g_x2b);  __nv_bfloat16* x2b  = (__nv_bfloat16*)p;
    cudaGetSymbolAddress(&p, g_qb);   __nv_bfloat16* qb   = (__nv_bfloat16*)p;
    cudaGetSymbolAddress(&p, g_kb);   __nv_bfloat16* kb   = (__nv_bfloat16*)p;
    cudaGetSymbolAddress(&p, g_vtb);  __nv_bfloat16* vtb  = (__nv_bfloat16*)p;
    cudaGetSymbolAddress(&p, g_yb);   __nv_bfloat16* yb   = (__nv_bfloat16*)p;
    cudaGetSymbolAddress(&p, g_hb);   __nv_bfloat16* hb   = (__nv_bfloat16*)p;
    cudaGetSymbolAddress(&p, g_vawT); __nv_bfloat16* vawT = (__nv_bfloat16*)p;
    cudaGetSymbolAddress(&p, g_wT);   __nv_bfloat16* wT   = (__nv_bfloat16*)p;
    cudaGetSymbolAddress(&p, g_f1T);  __nv_bfloat16* f1T  = (__nv_bfloat16*)p;
    cudaGetSymbolAddress(&p, g_f2T);  __nv_bfloat16* f2T  = (__nv_bfloat16*)p;
    const size_t WSZ = (size_t)DMODEL * DMODEL;

    conv(emb, eb, (long)VOCAB * DMODEL);
    convT(emb, ebT, VOCAB, DMODEL);
    conv(tgt, tgtb, (long)MD);
    conv(src, srcb, (long)MD);
    convT(va_w,  vawT,         2 * DMODEL, DMODEL);
    convT(sa_wq, wT + 0 * WSZ, DMODEL, DMODEL);
    convT(sa_wk, wT + 1 * WSZ, DMODEL, DMODEL);
    convT(sa_wv, wT + 2 * WSZ, DMODEL, DMODEL);
    convT(sa_wo, wT + 3 * WSZ, DMODEL, DMODEL);
    convT(ca_wq, wT + 4 * WSZ, DMODEL, DMODEL);
    convT(ca_wk, wT + 5 * WSZ, DMODEL, DMODEL);
    convT(ca_wv, wT + 6 * WSZ, DMODEL, DMODEL);
    convT(ca_wo, wT + 7 * WSZ, DMODEL, DMODEL);
    convT(ff_w1, f1T, DMODEL, DFF);
    convT(ff_w2, f2T, DFF, DMODEL);

    const float inv_sd = 1.0f / 32.0f;
    const long sQ = 65536, sS = 1048576;

    // ===== Vocabulary attention (softmax fused: exp in epilogue + row sums) ====
    zero_k<<<16, 256>>>(rs, 4096);
    tg(tgtb, eb, nullptr, Pb, 32, VOCAB, DMODEL, DMODEL, DMODEL, VOCAB, 128,
       1, 0,0,0,0,0,0,1,
       nullptr, nullptr, nullptr, nullptr, nullptr, 1.f, /*exp*/3, 0, rs);
    recip_k<<<16, 256>>>(rs, 4096);
    tg(Pb, ebT, nullptr, avb, 32, DMODEL, VOCAB, VOCAB, VOCAB, DMODEL, 128,
       1, 0,0,0,0,0,0,1, nullptr, nullptr, nullptr, nullptr, rs);
    tg(avb, vawT + DMODEL, tmp, nullptr, 32, DMODEL, DMODEL, DMODEL, 2 * DMODEL, DMODEL, 128);
    tg(tgtb, vawT, x1, x1b, 32, DMODEL, DMODEL, DMODEL, 2 * DMODEL, DMODEL, 128,
       1, 0,0,0,0,0,0,1, va_b, tmp, tgt, a_va);

    // ===== Self attention =====
    tg(x1b, wT + 0 * WSZ, nullptr, qb, 32, DMODEL, DMODEL, DMODEL, DMODEL, DMODEL, 128,
       1, 0,0,0,0,0,0,1, sa_bq, nullptr, nullptr, nullptr, nullptr, 1.f, 1, 1);
    tg(x1b, wT + 1 * WSZ, nullptr, kb, 32, DMODEL, DMODEL, DMODEL, DMODEL, DMODEL, 128,
       1, 0,0,0,0,0,0,1, sa_bk, nullptr, nullptr, nullptr, nullptr, 1.f, 1, 1);
    tg(x1b, wT + 2 * WSZ, nullptr, vtb, 32, DMODEL, DMODEL, DMODEL, DMODEL, DMODEL, 128,
       1, 0,0,0,0,0,0,1, sa_bv, nullptr, nullptr, nullptr, nullptr, 1.f, 1, 2);
    zero_k<<<256, 256>>>(rs, 65536);
    tg(qb, kb, nullptr, Pb, 8, 1024, 64, 64, 64, 1024, 128,
       64, sQ, 0, sQ, 0, sS, 0, 1,
       nullptr, nullptr, nullptr, nullptr, nullptr, inv_sd, 3, 0, rs);
    recip_k<<<256, 256>>>(rs, 65536);
    tg(Pb, vtb, nullptr, yb, 8, 64, 1024, 1024, 1024, DMODEL, 64,
       64, 16L * sS, sS, 16L * sQ, sQ, (long)1024 * DMODEL, 64, 16,
       nullptr, nullptr, nullptr, nullptr, rs);
    tg(yb, wT + 3 * WSZ, x2, x2b, 32, DMODEL, DMODEL, DMODEL, DMODEL, DMODEL, 128,
       1, 0,0,0,0,0,0,1, sa_bo, nullptr, x1, a_sa, nullptr, 1.f, 1, 0);

    // ===== Cross attention =====
    tg(x2b, wT + 4 * WSZ, nullptr, qb, 32, DMODEL, DMODEL, DMODEL, DMODEL, DMODEL, 128,
       1, 0,0,0,0,0,0,1, ca_bq, nullptr, nullptr, nullptr, nullptr, 1.f, 1, 1);
    tg(srcb, wT + 5 * WSZ, nullptr, kb, 32, DMODEL, DMODEL, DMODEL, DMODEL, DMODEL, 128,
       1, 0,0,0,0,0,0,1, ca_bk, nullptr, nullptr, nullptr, nullptr, 1.f, 1, 1);
    tg(srcb, wT + 6 * WSZ, nullptr, vtb, 32, DMODEL, DMODEL, DMODEL, DMODEL, DMODEL, 128,
       1, 0,0,0,0,0,0,1, ca_bv, nullptr, nullptr, nullptr, nullptr, 1.f, 1, 2);
    zero_k<<<256, 256>>>(rs, 65536);
    tg(qb, kb, nullptr, Pb, 8, 1024, 64, 64, 64, 1024, 128,
       64, sQ, 0, sQ, 0, sS, 0, 1,
       nullptr, nullptr, nullptr, nullptr, nullptr, inv_sd, 3, 0, rs);
    recip_k<<<256, 256>>>(rs, 65536);
    tg(Pb, vtb, nullptr, yb, 8, 64, 1024, 1024, 1024, DMODEL, 64,
       64, 16L * sS, sS, 16L * sQ, sQ, (long)1024 * DMODEL, 64, 16,
       nullptr, nullptr, nullptr, nullptr, rs);
    tg(yb, wT + 7 * WSZ, x1, x1b, 32, DMODEL, DMODEL, DMODEL, DMODEL, DMODEL, 128,
       1, 0,0,0,0,0,0,1, ca_bo, nullptr, x2, a_ca, nullptr, 1.f, 1, 0);

    // ===== Feed forward =====
    tg(x1b, f1T, nullptr, hb, 32, DFF, DMODEL, DMODEL, DMODEL, DFF, 128,
       1, 0,0,0,0,0,0,1, ff_b1, nullptr, nullptr, nullptr, nullptr, 1.f, 2, 0);
    tg(hb, f2T, out, nullptr, 32, DMODEL, DFF, DFF, DFF, DMODEL, 128,
       1, 0,0,0,0,0,0,1, ff_b2, nullptr, x1, a_ff, nullptr, 1.f, 0, 0);
}